// round 13
// baseline (speedup 1.0000x reference)
#include <cuda_runtime.h>
#include <cuda_fp16.h>
#include <cstdint>

#define BB 4
#define CHC 64
#define HH 128
#define WW 128
#define HWS (HH*WW)

// ---------------- scratch (no allocations allowed) ----------------
__device__ __align__(256) __half d_nbh_h[BB*HWS*CHC];      // NHWC fp16
__device__ __align__(256) __half d_cen_h[BB*HWS*CHC];
__device__ __align__(256) __half d_gH[BB*HWS*CHC];         // conv(nbh) NHWC fp16
__device__ __align__(256) __half d_cH[BB*HWS*CHC];         // conv(cen) NHWC fp16
__device__ __align__(256) __half d_wcomb[2*9*CHC*CHC];     // [conv][tap][o][c] fp16
__device__ __align__(256) __half d_w2h[9*CHC];             // w2 fp16

// ---------------- PTX helpers (portable sm_80+ subset only) ----------------
__device__ __forceinline__ uint32_t smem_u32(const void* p) {
    uint32_t a;
    asm("{ .reg .u64 t; cvta.to.shared.u64 t, %1; cvt.u32.u64 %0, t; }" : "=r"(a) : "l"(p));
    return a;
}
__device__ __forceinline__ void cpa16(uint32_t dst, const void* src) {
    asm volatile("cp.async.cg.shared.global [%0], [%1], 16;" :: "r"(dst), "l"(src));
}
__device__ __forceinline__ void ldsm4(uint32_t* r, uint32_t addr) {
    asm volatile("ldmatrix.sync.aligned.m8n8.x4.shared.b16 {%0,%1,%2,%3}, [%4];"
        : "=r"(r[0]), "=r"(r[1]), "=r"(r[2]), "=r"(r[3]) : "r"(addr));
}
__device__ __forceinline__ void mma_fp16(float* d, const uint32_t* a, const uint32_t* b) {
    asm volatile("mma.sync.aligned.m16n8k16.row.col.f32.f16.f16.f32 "
        "{%0,%1,%2,%3}, {%4,%5,%6,%7}, {%8,%9}, {%0,%1,%2,%3};"
        : "+f"(d[0]), "+f"(d[1]), "+f"(d[2]), "+f"(d[3])
        : "r"(a[0]), "r"(a[1]), "r"(a[2]), "r"(a[3]), "r"(b[0]), "r"(b[1]));
}
__device__ __forceinline__ void h8_to_f(const uint4& u, float* f) {
    const __half2* h = (const __half2*)&u;
    float2 t;
    t = __half22float2(h[0]); f[0] = t.x; f[1] = t.y;
    t = __half22float2(h[1]); f[2] = t.x; f[3] = t.y;
    t = __half22float2(h[2]); f[4] = t.x; f[5] = t.y;
    t = __half22float2(h[3]); f[6] = t.x; f[7] = t.y;
}

// ---------------- transpose NCHW->NHWC (fp16) + weight prep (proven R10 version) ----------------
__global__ void transpose_prep(const float* __restrict__ nbh, const float* __restrict__ cen,
                               __half* __restrict__ nh, __half* __restrict__ ch,
                               const float* __restrict__ w1, const float* __restrict__ w2,
                               __half* __restrict__ wcomb, __half* __restrict__ w2h)
{
    if (blockIdx.z == 8) {
        int idx = (blockIdx.y * gridDim.x + blockIdx.x) * 256 + threadIdx.y * 32 + threadIdx.x;
        if (idx < 2*9*4096) {
            int c = idx & 63;
            int o = (idx >> 6) & 63;
            int tap = (idx >> 12) % 9;
            int conv = idx / (9 * 4096);
            wcomb[idx] = __float2half(w1[o * 1152 + conv * 576 + c * 9 + tap]);
        } else if (idx < 2*9*4096 + 9*CHC) {
            int k = idx - 2*9*4096;
            w2h[k] = __float2half(w2[k]);
        }
        return;
    }
    __shared__ float tile[32][33];
    int which = blockIdx.z >> 2;
    int b = blockIdx.z & 3;
    const float* inb = (which ? cen : nbh) + (size_t)b * CHC * HWS;
    __half* oh = which ? ch : nh;
    int c0 = blockIdx.x * 32;
    int r0 = blockIdx.y * 32;
#pragma unroll
    for (int i = 0; i < 32; i += 8)
        tile[threadIdx.y + i][threadIdx.x] =
            inb[(size_t)(r0 + threadIdx.y + i) * HWS + (c0 + threadIdx.x)];
    __syncthreads();
#pragma unroll
    for (int i = 0; i < 32; i += 8) {
        float v = tile[threadIdx.x][threadIdx.y + i];
        int px = c0 + threadIdx.y + i;
        int chn = r0 + threadIdx.x;
        oh[((size_t)b * HWS + px) * 64 + chn] = __float2half(v);
    }
}

// ---------------- HMMA dual conv3x3: CTA M512xN64, 8 warps M64xN64 (R12 proven) ----------------
#define A_BYTES (780*128)
#define W_OFF   A_BYTES
#define CONV_SMEM (A_BYTES + 9*64*128)

__global__ void __launch_bounds__(256, 1) conv_tc(
    const __half* __restrict__ nbh_h,
    const __half* __restrict__ cen_h,
    const __half* __restrict__ wcomb,
    __half* __restrict__ gH, __half* __restrict__ cH)
{
    extern __shared__ char smem[];
    const int tid = threadIdx.x;
    const int lane = tid & 31;
    const int wid = tid >> 5;
    const int y0 = blockIdx.x * 4;
    const int b = blockIdx.y;
    const int conv = blockIdx.z;
    const __half* src = conv ? cen_h : nbh_h;
    __half* outp = conv ? cH : gH;
    const __half* wsrc = wcomb + (size_t)conv * 9 * 4096;
    const uint32_t sb = smem_u32(smem);

#pragma unroll
    for (int it = 0; it < 24; ++it) {
        int i = tid + it * 256;
        int px = i >> 3, chn = i & 7;
        int ry = px >> 7, x = px & 127;
        int yy = y0 - 1 + ry;
        int pxb = ry * 130 + x + 1;
        uint32_t off = (uint32_t)pxb * 128 + (((uint32_t)chn ^ (pxb & 7)) << 4);
        if ((unsigned)yy < 128u)
            cpa16(sb + off, src + (((size_t)((b * 128 + yy) * 128 + x)) << 6) + chn * 8);
        else
            *(uint4*)(smem + off) = make_uint4(0u, 0u, 0u, 0u);
    }
    if (tid < 96) {
        int pp = tid >> 3;
        int ry = pp >> 1;
        int xpad = (pp & 1) ? 129 : 0;
        int pxb = ry * 130 + xpad;
        int chn = tid & 7;
        uint32_t off = (uint32_t)pxb * 128 + (((uint32_t)chn ^ (pxb & 7)) << 4);
        *(uint4*)(smem + off) = make_uint4(0u, 0u, 0u, 0u);
    }
#pragma unroll
    for (int it = 0; it < 18; ++it) {
        int i = tid + it * 256;
        int row = i >> 3, chn = i & 7;
        uint32_t off = W_OFF + (uint32_t)row * 128 + (((uint32_t)chn ^ (row & 7)) << 4);
        cpa16(sb + off, wsrc + row * 64 + chn * 8);
    }
    asm volatile("cp.async.commit_group;");
    asm volatile("cp.async.wait_group 0;");
    __syncthreads();

    float acc[4][8][4];
#pragma unroll
    for (int mt = 0; mt < 4; ++mt)
#pragma unroll
        for (int nt = 0; nt < 8; ++nt)
#pragma unroll
            for (int q = 0; q < 4; ++q) acc[mt][nt][q] = 0.f;

    const int chalfA = lane >> 4;
    const int chalfB = (lane >> 3) & 1;
    const int o_ld = (lane & 7) + ((lane >> 4) << 3);
    const uint32_t bsw = ((uint32_t)(o_ld & 7)) << 4;
    const uint32_t browb = sb + W_OFF + (uint32_t)o_ld * 128;

    int mbase[4], mx[4];
#pragma unroll
    for (int mt = 0; mt < 4; ++mt) {
        int m = wid * 64 + mt * 16 + (lane & 15);
        mbase[mt] = (m >> 7);
        mx[mt] = m & 127;
    }

#pragma unroll
    for (int t = 0; t < 9; ++t) {
        const int dy = t / 3 - 1, dx = t % 3 - 1;
        uint32_t arow[4], asw[4];
#pragma unroll
        for (int mt = 0; mt < 4; ++mt) {
            int pxb = (mbase[mt] + dy + 1) * 130 + (mx[mt] + dx + 1);
            arow[mt] = sb + (uint32_t)pxb * 128;
            asw[mt] = ((uint32_t)(pxb & 7)) << 4;
        }
        const uint32_t browt = browb + (uint32_t)t * 64 * 128;

#pragma unroll
        for (int ks = 0; ks < 4; ++ks) {
            const uint32_t chi = (uint32_t)(ks * 2 + chalfA) << 4;
            uint32_t a[4][4];
#pragma unroll
            for (int mt = 0; mt < 4; ++mt)
                ldsm4(a[mt], arow[mt] + (chi ^ asw[mt]));
            const uint32_t cbi = (uint32_t)(ks * 2 + chalfB) << 4;
            uint32_t bv[4][4];
#pragma unroll
            for (int j = 0; j < 4; ++j)
                ldsm4(bv[j], browt + (uint32_t)j * 16 * 128 + (cbi ^ bsw));
#pragma unroll
            for (int mt = 0; mt < 4; ++mt)
#pragma unroll
                for (int j = 0; j < 4; ++j) {
                    mma_fp16(acc[mt][2*j],   a[mt], &bv[j][0]);
                    mma_fp16(acc[mt][2*j+1], a[mt], &bv[j][2]);
                }
        }
    }

#pragma unroll
    for (int mt = 0; mt < 4; ++mt) {
        int m0 = wid * 64 + mt * 16 + (lane >> 2);
#pragma unroll
        for (int half = 0; half < 2; ++half) {
            int m = m0 + half * 8;
            int y = y0 + (m >> 7), x = m & 127;
            __half2* rowp = (__half2*)(outp + (((size_t)((b * 128 + y) * 128 + x)) << 6));
#pragma unroll
            for (int nt = 0; nt < 8; ++nt) {
                int o = nt * 8 + (lane & 3) * 2;
                rowp[o >> 1] = __floats2half2_rn(acc[mt][nt][half * 2], acc[mt][nt][half * 2 + 1]);
            }
        }
    }
}

// ---------------- fused attn: 8 px/warp, 4 lanes/px, 16 ch/lane ----------------
__global__ void __launch_bounds__(256) fused_attn(
    const __half* __restrict__ gH, const __half* __restrict__ cH,
    const __half* __restrict__ nbh_h, const float* __restrict__ mv,
    const float* __restrict__ b1, const __half* __restrict__ w2h,
    const float* __restrict__ b2, float* __restrict__ out)
{
    __shared__ float sout[64][65];   // [local px][channel]

    int lane = threadIdx.x & 31;
    int wid = threadIdx.x >> 5;
    int grp = lane >> 2;          // pixel within warp (0..7)
    int lg = lane & 3;            // lane within pixel group; channels lg*16..lg*16+15
    int pxl = wid * 8 + grp;      // local pixel 0..63
    int pixg = blockIdx.x * 64 + pxl;
    int b = pixg >> 14;
    int pix = pixg & (HWS - 1);
    int y = pix >> 7, x = pix & 127;

    float mvx = mv[(b*2 + 0)*HWS + pix];
    float mvy = mv[(b*2 + 1)*HWS + pix];
    const float inv = 2.0f / 127.0f;
    float gx = fminf(fmaxf(-1.0f + inv*(float)x + mvx*0.5f, -1.0f), 1.0f);
    float gy = fminf(fmaxf(-1.0f + inv*(float)y + mvy*0.5f, -1.0f), 1.0f);
    float px = (gx + 1.0f) * 0.5f * 127.0f;
    float py = (gy + 1.0f) * 0.5f * 127.0f;
    float fx0 = floorf(px), fy0 = floorf(py);
    float wx = px - fx0, wy = py - fy0;
    int ix0 = min(max((int)fx0, 0), WW - 1);
    int iy0 = min(max((int)fy0, 0), HH - 1);
    int ix1 = min(ix0 + 1, WW - 1);
    int iy1 = min(iy0 + 1, HH - 1);

    int pbase = b * HWS;
    const uint4* g4 = (const uint4*)gH;
    const uint4* c4 = (const uint4*)cH;
    float w00 = (1.f-wx)*(1.f-wy), w01 = wx*(1.f-wy), w10 = (1.f-wx)*wy, w11 = wx*wy;

    size_t p00 = (size_t)(pbase + iy0*WW + ix0)*8;
    size_t p01 = (size_t)(pbase + iy0*WW + ix1)*8;
    size_t p10 = (size_t)(pbase + iy1*WW + ix0)*8;
    size_t p11 = (size_t)(pbase + iy1*WW + ix1)*8;
    size_t pcn = (size_t)(pbase + pix)*8;

    float h1[16];
#pragma unroll
    for (int hh = 0; hh < 2; ++hh) {
        int i8 = lg*2 + hh;                // uint4 index within pixel row
        uint4 r00 = g4[p00 + i8];
        uint4 r01 = g4[p01 + i8];
        uint4 r10 = g4[p10 + i8];
        uint4 r11 = g4[p11 + i8];
        uint4 rcn = c4[pcn + i8];
        float f00[8], f01[8], f10[8], f11[8], fcn[8];
        h8_to_f(r00, f00); h8_to_f(r01, f01); h8_to_f(r10, f10); h8_to_f(r11, f11);
        h8_to_f(rcn, fcn);
        float4 ba = ((const float4*)b1)[i8*2];
        float4 bb = ((const float4*)b1)[i8*2 + 1];
        float bv[8] = {ba.x, ba.y, ba.z, ba.w, bb.x, bb.y, bb.z, bb.w};
#pragma unroll
        for (int i = 0; i < 8; ++i) {
            float v = f00[i]*w00 + f01[i]*w01 + f10[i]*w10 + f11[i]*w11 + fcn[i] + bv[i];
            h1[hh*8 + i] = v >= 0.f ? v : 0.1f*v;
        }
    }

    float part[9];
    const uint4* w24 = (const uint4*)w2h;
#pragma unroll
    for (int j = 0; j < 9; ++j) {
        float s = 0.f;
#pragma unroll
        for (int hh = 0; hh < 2; ++hh) {
            float wv[8];
            h8_to_f(w24[j*8 + lg*2 + hh], wv);
#pragma unroll
            for (int i = 0; i < 8; ++i) s += h1[hh*8 + i] * wv[i];
        }
        part[j] = s;
    }
#pragma unroll
    for (int off = 1; off < 4; off <<= 1)
#pragma unroll
        for (int j = 0; j < 9; ++j)
            part[j] += __shfl_xor_sync(0xffffffffu, part[j], off);

    float mx = -1e30f;
#pragma unroll
    for (int j = 0; j < 9; ++j) { part[j] += b2[j]; mx = fmaxf(mx, part[j]); }
    float s = 0.f;
    float attn[9];
#pragma unroll
    for (int j = 0; j < 9; ++j) { attn[j] = __expf(part[j] - mx); s += attn[j]; }
    float sc = 1.0f / (9.0f * s);
#pragma unroll
    for (int j = 0; j < 9; ++j) attn[j] *= sc;

    float wyv[2] = {1.f - wy, wy};
    float wxv[2] = {1.f - wx, wx};
    int d1y = iy1 - iy0;
    int d1x = ix1 - ix0;
    float Wrow[3][4], Wcol[3][4];
#pragma unroll
    for (int dy = 0; dy < 3; ++dy)
#pragma unroll
        for (int r = 0; r < 4; ++r) { Wrow[dy][r] = 0.f; Wcol[dy][r] = 0.f; }
#pragma unroll
    for (int dy = 0; dy < 3; ++dy) {
        int rowlo = iy0 + dy - 1;
        float vlo = (rowlo >= 0 && rowlo < HH) ? wyv[0] : 0.f;
        Wrow[dy][dy] += vlo;
        int rowhi = iy1 + dy - 1;
        float vhi = (rowhi >= 0 && rowhi < HH) ? wyv[1] : 0.f;
        if (d1y) Wrow[dy][dy+1] += vhi; else Wrow[dy][dy] += vhi;

        int collo = ix0 + dy - 1;
        float ulo = (collo >= 0 && collo < WW) ? wxv[0] : 0.f;
        Wcol[dy][dy] += ulo;
        int colhi = ix1 + dy - 1;
        float uhi = (colhi >= 0 && colhi < WW) ? wxv[1] : 0.f;
        if (d1x) Wcol[dy][dy+1] += uhi; else Wcol[dy][dy] += uhi;
    }
    float tmp[3][4];
#pragma unroll
    for (int dy = 0; dy < 3; ++dy)
#pragma unroll
        for (int sx = 0; sx < 4; ++sx) {
            float t = 0.f;
#pragma unroll
            for (int dx = 0; dx < 3; ++dx) t += attn[dy*3 + dx] * Wcol[dx][sx];
            tmp[dy][sx] = t;
        }
    float coeff[16];
#pragma unroll
    for (int r = 0; r < 4; ++r)
#pragma unroll
        for (int sx = 0; sx < 4; ++sx) {
            float t = 0.f;
#pragma unroll
            for (int dy = 0; dy < 3; ++dy) t += Wrow[dy][r] * tmp[dy][sx];
            coeff[r*4 + sx] = t;
        }

    int rowi[4], coli[4];
#pragma unroll
    for (int r = 0; r < 4; ++r) rowi[r] = min(max(iy0 - 1 + r, 0), HH - 1);
#pragma unroll
    for (int sx = 0; sx < 4; ++sx) coli[sx] = min(max(ix0 - 1 + sx, 0), WW - 1);

    const uint4* n4 = (const uint4*)nbh_h;
    float o[16];
#pragma unroll
    for (int i = 0; i < 16; ++i) o[i] = 0.f;
#pragma unroll
    for (int r = 0; r < 4; ++r) {
        size_t rb = (size_t)(pbase + rowi[r]*WW)*8 + lg*2;
#pragma unroll
        for (int sx = 0; sx < 4; ++sx) {
            size_t base = rb + (size_t)coli[sx]*8;
            uint4 v0 = n4[base];
            uint4 v1 = n4[base + 1];
            float cf = coeff[r*4 + sx];
            float fv[8];
            h8_to_f(v0, fv);
#pragma unroll
            for (int i = 0; i < 8; ++i) o[i] += cf * fv[i];
            h8_to_f(v1, fv);
#pragma unroll
            for (int i = 0; i < 8; ++i) o[8 + i] += cf * fv[i];
        }
    }

#pragma unroll
    for (int i = 0; i < 16; ++i)
        sout[pxl][lg*16 + i] = o[i];
    __syncthreads();

    // write NCHW: 64-px contiguous runs per channel
    int pix0 = (blockIdx.x * 64) & (HWS - 1);
    int bw = (blockIdx.x * 64) >> 14;
    int px2 = threadIdx.x & 63;
    int cg = (threadIdx.x >> 6) * 16;
    float* ob = out + (size_t)bw * 64 * HWS + pix0 + px2;
#pragma unroll
    for (int i = 0; i < 16; ++i)
        ob[(size_t)(cg + i) * HWS] = sout[px2][cg + i];
}

// ---------------- launcher ----------------
extern "C" void kernel_launch(void* const* d_in, const int* in_sizes, int n_in,
                              void* d_out, int out_size)
{
    const float* nbh = (const float*)d_in[0];
    const float* cen = (const float*)d_in[1];
    const float* mv  = (const float*)d_in[2];
    const float* w1  = (const float*)d_in[3];
    const float* b1  = (const float*)d_in[4];
    const float* w2  = (const float*)d_in[5];
    const float* b2  = (const float*)d_in[6];
    float* out = (float*)d_out;

    __half *nh, *ch, *gH, *cH, *wc, *w2h;
    cudaGetSymbolAddress((void**)&nh,   d_nbh_h);
    cudaGetSymbolAddress((void**)&ch,   d_cen_h);
    cudaGetSymbolAddress((void**)&gH,   d_gH);
    cudaGetSymbolAddress((void**)&cH,   d_cH);
    cudaGetSymbolAddress((void**)&wc,   d_wcomb);
    cudaGetSymbolAddress((void**)&w2h,  d_w2h);

    cudaFuncSetAttribute(conv_tc, cudaFuncAttributeMaxDynamicSharedMemorySize, CONV_SMEM);

    // NCHW -> NHWC fp16 + weight prep
    transpose_prep<<<dim3(HWS/32, CHC/32, 9), dim3(32, 8)>>>(nbh, cen, nh, ch, w1, w2, wc, w2h);

    // HMMA dual conv: CTA M512xN64
    conv_tc<<<dim3(HH/4, BB, 2), 256, CONV_SMEM>>>(nh, ch, wc, gH, cH);

    // 8 px/warp, 8 warps/block -> 64 px/block; writes NCHW directly
    fused_attn<<<BB*HWS/64, 256>>>(gH, cH, nh, mv, b1, w2h, b2, out);
}

// round 14
// speedup vs baseline: 1.0556x; 1.0556x over previous
#include <cuda_runtime.h>
#include <cuda_fp16.h>
#include <cstdint>

#define BB 4
#define CHC 64
#define HH 128
#define WW 128
#define HWS (HH*WW)

// ---------------- scratch (no allocations allowed) ----------------
__device__ __align__(256) __half d_nbh_h[BB*HWS*CHC];      // NHWC fp16
__device__ __align__(256) __half d_cen_h[BB*HWS*CHC];
__device__ __align__(256) __half d_gH[BB*HWS*CHC];         // conv(nbh) NHWC fp16
__device__ __align__(256) __half d_cH[BB*HWS*CHC];         // conv(cen) NHWC fp16
__device__ __align__(256) __half d_wcomb[2*9*CHC*CHC];     // [conv][tap][o][c] fp16
__device__ __align__(256) __half d_w2h[9*CHC];             // w2 fp16

// ---------------- PTX helpers (portable sm_80+ subset only) ----------------
__device__ __forceinline__ uint32_t smem_u32(const void* p) {
    uint32_t a;
    asm("{ .reg .u64 t; cvta.to.shared.u64 t, %1; cvt.u32.u64 %0, t; }" : "=r"(a) : "l"(p));
    return a;
}
__device__ __forceinline__ void cpa16(uint32_t dst, const void* src) {
    asm volatile("cp.async.cg.shared.global [%0], [%1], 16;" :: "r"(dst), "l"(src));
}
__device__ __forceinline__ void ldsm4(uint32_t* r, uint32_t addr) {
    asm volatile("ldmatrix.sync.aligned.m8n8.x4.shared.b16 {%0,%1,%2,%3}, [%4];"
        : "=r"(r[0]), "=r"(r[1]), "=r"(r[2]), "=r"(r[3]) : "r"(addr));
}
__device__ __forceinline__ void mma_fp16(float* d, const uint32_t* a, const uint32_t* b) {
    asm volatile("mma.sync.aligned.m16n8k16.row.col.f32.f16.f16.f32 "
        "{%0,%1,%2,%3}, {%4,%5,%6,%7}, {%8,%9}, {%0,%1,%2,%3};"
        : "+f"(d[0]), "+f"(d[1]), "+f"(d[2]), "+f"(d[3])
        : "r"(a[0]), "r"(a[1]), "r"(a[2]), "r"(a[3]), "r"(b[0]), "r"(b[1]));
}
__device__ __forceinline__ void h8_to_f(const uint4& u, float* f) {
    const __half2* h = (const __half2*)&u;
    float2 t;
    t = __half22float2(h[0]); f[0] = t.x; f[1] = t.y;
    t = __half22float2(h[1]); f[2] = t.x; f[3] = t.y;
    t = __half22float2(h[2]); f[4] = t.x; f[5] = t.y;
    t = __half22float2(h[3]); f[6] = t.x; f[7] = t.y;
}

// ---------------- transpose NCHW->NHWC (fp16) + weight prep (proven R10 version) ----------------
__global__ void transpose_prep(const float* __restrict__ nbh, const float* __restrict__ cen,
                               __half* __restrict__ nh, __half* __restrict__ ch,
                               const float* __restrict__ w1, const float* __restrict__ w2,
                               __half* __restrict__ wcomb, __half* __restrict__ w2h)
{
    if (blockIdx.z == 8) {
        int idx = (blockIdx.y * gridDim.x + blockIdx.x) * 256 + threadIdx.y * 32 + threadIdx.x;
        if (idx < 2*9*4096) {
            int c = idx & 63;
            int o = (idx >> 6) & 63;
            int tap = (idx >> 12) % 9;
            int conv = idx / (9 * 4096);
            wcomb[idx] = __float2half(w1[o * 1152 + conv * 576 + c * 9 + tap]);
        } else if (idx < 2*9*4096 + 9*CHC) {
            int k = idx - 2*9*4096;
            w2h[k] = __float2half(w2[k]);
        }
        return;
    }
    __shared__ float tile[32][33];
    int which = blockIdx.z >> 2;
    int b = blockIdx.z & 3;
    const float* inb = (which ? cen : nbh) + (size_t)b * CHC * HWS;
    __half* oh = which ? ch : nh;
    int c0 = blockIdx.x * 32;
    int r0 = blockIdx.y * 32;
#pragma unroll
    for (int i = 0; i < 32; i += 8)
        tile[threadIdx.y + i][threadIdx.x] =
            inb[(size_t)(r0 + threadIdx.y + i) * HWS + (c0 + threadIdx.x)];
    __syncthreads();
#pragma unroll
    for (int i = 0; i < 32; i += 8) {
        float v = tile[threadIdx.x][threadIdx.y + i];
        int px = c0 + threadIdx.y + i;
        int chn = r0 + threadIdx.x;
        oh[((size_t)b * HWS + px) * 64 + chn] = __float2half(v);
    }
}

// ---------------- HMMA dual conv3x3: CTA M512xN64, pipelined W, smem epilogue ----------------
#define A_BYTES (780*128)
#define W_OFF   A_BYTES
#define CONV_SMEM (A_BYTES + 9*64*128)

__global__ void __launch_bounds__(256, 1) conv_tc(
    const __half* __restrict__ nbh_h,
    const __half* __restrict__ cen_h,
    const __half* __restrict__ wcomb,
    __half* __restrict__ gH, __half* __restrict__ cH)
{
    extern __shared__ char smem[];
    const int tid = threadIdx.x;
    const int lane = tid & 31;
    const int wid = tid >> 5;
    const int y0 = blockIdx.x * 4;
    const int b = blockIdx.y;
    const int conv = blockIdx.z;
    const __half* src = conv ? cen_h : nbh_h;
    __half* outp = conv ? cH : gH;
    const __half* wsrc = wcomb + (size_t)conv * 9 * 4096;
    const uint32_t sb = smem_u32(smem);

    // ---- stage A: rows y0-1..y0+4 ----
#pragma unroll
    for (int it = 0; it < 24; ++it) {
        int i = tid + it * 256;
        int px = i >> 3, chn = i & 7;
        int ry = px >> 7, x = px & 127;
        int yy = y0 - 1 + ry;
        int pxb = ry * 130 + x + 1;
        uint32_t off = (uint32_t)pxb * 128 + (((uint32_t)chn ^ (pxb & 7)) << 4);
        if ((unsigned)yy < 128u)
            cpa16(sb + off, src + (((size_t)((b * 128 + yy) * 128 + x)) << 6) + chn * 8);
        else
            *(uint4*)(smem + off) = make_uint4(0u, 0u, 0u, 0u);
    }
    if (tid < 96) {
        int pp = tid >> 3;
        int ry = pp >> 1;
        int xpad = (pp & 1) ? 129 : 0;
        int pxb = ry * 130 + xpad;
        int chn = tid & 7;
        uint32_t off = (uint32_t)pxb * 128 + (((uint32_t)chn ^ (pxb & 7)) << 4);
        *(uint4*)(smem + off) = make_uint4(0u, 0u, 0u, 0u);
    }
    // ---- stage W in 3 pipelined groups: taps 0-2 (with A), 3-5, 6-8 ----
#pragma unroll
    for (int g = 0; g < 3; ++g) {
#pragma unroll
        for (int it = 0; it < 6; ++it) {
            int i = tid + it * 256 + g * 1536;     // row = i>>3 spans 192 rows per group
            int row = i >> 3, chn = i & 7;
            uint32_t off = W_OFF + (uint32_t)row * 128 + (((uint32_t)chn ^ (row & 7)) << 4);
            cpa16(sb + off, wsrc + row * 64 + chn * 8);
        }
        asm volatile("cp.async.commit_group;");
    }

    float acc[4][8][4];
#pragma unroll
    for (int mt = 0; mt < 4; ++mt)
#pragma unroll
        for (int nt = 0; nt < 8; ++nt)
#pragma unroll
            for (int q = 0; q < 4; ++q) acc[mt][nt][q] = 0.f;

    const int chalfA = lane >> 4;
    const int chalfB = (lane >> 3) & 1;
    const int o_ld = (lane & 7) + ((lane >> 4) << 3);
    const uint32_t bsw = ((uint32_t)(o_ld & 7)) << 4;
    const uint32_t browb = sb + W_OFF + (uint32_t)o_ld * 128;

    int mbase[4], mxx[4];
#pragma unroll
    for (int mt = 0; mt < 4; ++mt) {
        int m = wid * 64 + mt * 16 + (lane & 15);
        mbase[mt] = (m >> 7);
        mxx[mt] = m & 127;
    }

    auto do_taps = [&](int t0) {
#pragma unroll
        for (int tt = 0; tt < 3; ++tt) {
            const int t = t0 + tt;
            const int dy = t / 3 - 1, dx = t % 3 - 1;
            uint32_t arow[4], asw[4];
#pragma unroll
            for (int mt = 0; mt < 4; ++mt) {
                int pxb = (mbase[mt] + dy + 1) * 130 + (mxx[mt] + dx + 1);
                arow[mt] = sb + (uint32_t)pxb * 128;
                asw[mt] = ((uint32_t)(pxb & 7)) << 4;
            }
            const uint32_t browt = browb + (uint32_t)t * 64 * 128;
#pragma unroll
            for (int ks = 0; ks < 4; ++ks) {
                const uint32_t chi = (uint32_t)(ks * 2 + chalfA) << 4;
                uint32_t a[4][4];
#pragma unroll
                for (int mt = 0; mt < 4; ++mt)
                    ldsm4(a[mt], arow[mt] + (chi ^ asw[mt]));
                const uint32_t cbi = (uint32_t)(ks * 2 + chalfB) << 4;
                uint32_t bv[4][4];
#pragma unroll
                for (int j = 0; j < 4; ++j)
                    ldsm4(bv[j], browt + (uint32_t)j * 16 * 128 + (cbi ^ bsw));
#pragma unroll
                for (int mt = 0; mt < 4; ++mt)
#pragma unroll
                    for (int j = 0; j < 4; ++j) {
                        mma_fp16(acc[mt][2*j],   a[mt], &bv[j][0]);
                        mma_fp16(acc[mt][2*j+1], a[mt], &bv[j][2]);
                    }
            }
        }
    };

    asm volatile("cp.async.wait_group 2;");
    __syncthreads();
    do_taps(0);
    asm volatile("cp.async.wait_group 1;");
    __syncthreads();
    do_taps(3);
    asm volatile("cp.async.wait_group 0;");
    __syncthreads();
    do_taps(6);

    // ---- epilogue: acc -> smem (swizzled, conflict-free) -> coalesced STG.128 ----
    __syncthreads();   // A region no longer needed
#pragma unroll
    for (int mt = 0; mt < 4; ++mt)
#pragma unroll
        for (int half = 0; half < 2; ++half) {
            int px = wid * 64 + mt * 16 + (lane >> 2) + half * 8;
#pragma unroll
            for (int nt = 0; nt < 8; ++nt) {
                __half2 hv = __floats2half2_rn(acc[mt][nt][half * 2], acc[mt][nt][half * 2 + 1]);
                uint32_t so = (uint32_t)px * 128 + (((uint32_t)nt ^ (px & 7)) << 4) + (lane & 3) * 4;
                *(uint32_t*)(smem + so) = *(uint32_t*)&hv;
            }
        }
    __syncthreads();
    char* gb = (char*)outp + ((size_t)((b * 128 + y0) * 128) << 7);  // *64ch*2B = <<7
#pragma unroll
    for (int it = 0; it < 16; ++it) {
        int i = tid + it * 256;
        int px = i >> 3, chunk = i & 7;
        uint32_t so = (uint32_t)px * 128 + (((uint32_t)(chunk ^ (px & 7))) << 4);
        *(uint4*)(gb + (size_t)px * 128 + chunk * 16) = *(uint4*)(smem + so);
    }
}

// ---------------- fused attn: 4 px/warp (R12 proven); writes NCHW fp32 via smem ----------------
__global__ void __launch_bounds__(256) fused_attn(
    const __half* __restrict__ gH, const __half* __restrict__ cH,
    const __half* __restrict__ nbh_h, const float* __restrict__ mv,
    const float* __restrict__ b1, const __half* __restrict__ w2h,
    const float* __restrict__ b2, float* __restrict__ out)
{
    __shared__ float sout[32][65];

    int wg = blockIdx.x * 8 + (threadIdx.x >> 5);
    int lane = threadIdx.x & 31;
    int grp = lane >> 3;
    int lg = lane & 7;
    int pxl = ((threadIdx.x >> 5) << 2) | grp;
    int pixg = wg * 4 + grp;
    int b = pixg >> 14;
    int pix = pixg & (HWS - 1);
    int y = pix >> 7, x = pix & 127;

    float mvx = mv[(b*2 + 0)*HWS + pix];
    float mvy = mv[(b*2 + 1)*HWS + pix];
    const float inv = 2.0f / 127.0f;
    float gx = fminf(fmaxf(-1.0f + inv*(float)x + mvx*0.5f, -1.0f), 1.0f);
    float gy = fminf(fmaxf(-1.0f + inv*(float)y + mvy*0.5f, -1.0f), 1.0f);
    float px = (gx + 1.0f) * 0.5f * 127.0f;
    float py = (gy + 1.0f) * 0.5f * 127.0f;
    float fx0 = floorf(px), fy0 = floorf(py);
    float wx = px - fx0, wy = py - fy0;
    int ix0 = min(max((int)fx0, 0), WW - 1);
    int iy0 = min(max((int)fy0, 0), HH - 1);
    int ix1 = min(ix0 + 1, WW - 1);
    int iy1 = min(iy0 + 1, HH - 1);

    int pbase = b * HWS;
    const uint4* g4 = (const uint4*)gH;
    uint4 r00 = g4[(size_t)(pbase + iy0*WW + ix0)*8 + lg];
    uint4 r01 = g4[(size_t)(pbase + iy0*WW + ix1)*8 + lg];
    uint4 r10 = g4[(size_t)(pbase + iy1*WW + ix0)*8 + lg];
    uint4 r11 = g4[(size_t)(pbase + iy1*WW + ix1)*8 + lg];
    uint4 rcn = ((const uint4*)cH)[(size_t)(pbase + pix)*8 + lg];
    float w00 = (1.f-wx)*(1.f-wy), w01 = wx*(1.f-wy), w10 = (1.f-wx)*wy, w11 = wx*wy;

    float f00[8], f01[8], f10[8], f11[8], fcn[8];
    h8_to_f(r00, f00); h8_to_f(r01, f01); h8_to_f(r10, f10); h8_to_f(r11, f11);
    h8_to_f(rcn, fcn);
    float4 b1a = ((const float4*)b1)[lg*2];
    float4 b1b = ((const float4*)b1)[lg*2 + 1];
    float b1v[8] = {b1a.x, b1a.y, b1a.z, b1a.w, b1b.x, b1b.y, b1b.z, b1b.w};

    float h1[8];
#pragma unroll
    for (int i = 0; i < 8; ++i) {
        float v = f00[i]*w00 + f01[i]*w01 + f10[i]*w10 + f11[i]*w11 + fcn[i] + b1v[i];
        h1[i] = v >= 0.f ? v : 0.1f*v;
    }

    float part[9];
    const uint4* w24 = (const uint4*)w2h;
#pragma unroll
    for (int j = 0; j < 9; ++j) {
        float wv[8];
        h8_to_f(w24[j*8 + lg], wv);
        part[j] = h1[0]*wv[0] + h1[1]*wv[1] + h1[2]*wv[2] + h1[3]*wv[3]
                + h1[4]*wv[4] + h1[5]*wv[5] + h1[6]*wv[6] + h1[7]*wv[7];
    }
#pragma unroll
    for (int off = 1; off < 8; off <<= 1)
#pragma unroll
        for (int j = 0; j < 9; ++j)
            part[j] += __shfl_xor_sync(0xffffffffu, part[j], off);

    float mx = -1e30f;
#pragma unroll
    for (int j = 0; j < 9; ++j) { part[j] += b2[j]; mx = fmaxf(mx, part[j]); }
    float s = 0.f;
    float attn[9];
#pragma unroll
    for (int j = 0; j < 9; ++j) { attn[j] = __expf(part[j] - mx); s += attn[j]; }
    float sc = 1.0f / (9.0f * s);
#pragma unroll
    for (int j = 0; j < 9; ++j) attn[j] *= sc;

    float wyv[2] = {1.f - wy, wy};
    float wxv[2] = {1.f - wx, wx};
    int d1y = iy1 - iy0;
    int d1x = ix1 - ix0;
    float Wrow[3][4], Wcol[3][4];
#pragma unroll
    for (int dy = 0; dy < 3; ++dy)
#pragma unroll
        for (int r = 0; r < 4; ++r) { Wrow[dy][r] = 0.f; Wcol[dy][r] = 0.f; }
#pragma unroll
    for (int dy = 0; dy < 3; ++dy) {
        int rowlo = iy0 + dy - 1;
        float vlo = (rowlo >= 0 && rowlo < HH) ? wyv[0] : 0.f;
        Wrow[dy][dy] += vlo;
        int rowhi = iy1 + dy - 1;
        float vhi = (rowhi >= 0 && rowhi < HH) ? wyv[1] : 0.f;
        if (d1y) Wrow[dy][dy+1] += vhi; else Wrow[dy][dy] += vhi;

        int collo = ix0 + dy - 1;
        float ulo = (collo >= 0 && collo < WW) ? wxv[0] : 0.f;
        Wcol[dy][dy] += ulo;
        int colhi = ix1 + dy - 1;
        float uhi = (colhi >= 0 && colhi < WW) ? wxv[1] : 0.f;
        if (d1x) Wcol[dy][dy+1] += uhi; else Wcol[dy][dy] += uhi;
    }
    float tmp[3][4];
#pragma unroll
    for (int dy = 0; dy < 3; ++dy)
#pragma unroll
        for (int sx = 0; sx < 4; ++sx) {
            float t = 0.f;
#pragma unroll
            for (int dx = 0; dx < 3; ++dx) t += attn[dy*3 + dx] * Wcol[dx][sx];
            tmp[dy][sx] = t;
        }
    float coeff[16];
#pragma unroll
    for (int r = 0; r < 4; ++r)
#pragma unroll
        for (int sx = 0; sx < 4; ++sx) {
            float t = 0.f;
#pragma unroll
            for (int dy = 0; dy < 3; ++dy) t += Wrow[dy][r] * tmp[dy][sx];
            coeff[r*4 + sx] = t;
        }

    int rowi[4], coli[4];
#pragma unroll
    for (int r = 0; r < 4; ++r) rowi[r] = min(max(iy0 - 1 + r, 0), HH - 1);
#pragma unroll
    for (int sx = 0; sx < 4; ++sx) coli[sx] = min(max(ix0 - 1 + sx, 0), WW - 1);

    const uint4* n4 = (const uint4*)nbh_h;
    float o[8];
#pragma unroll
    for (int i = 0; i < 8; ++i) o[i] = 0.f;
#pragma unroll
    for (int r = 0; r < 4; ++r) {
        size_t rb = (size_t)(pbase + rowi[r]*WW)*8 + lg;
#pragma unroll
        for (int sx = 0; sx < 4; ++sx) {
            uint4 v = n4[rb + (size_t)coli[sx]*8];
            float fv[8];
            h8_to_f(v, fv);
            float cf = coeff[r*4 + sx];
#pragma unroll
            for (int i = 0; i < 8; ++i) o[i] += cf * fv[i];
        }
    }

#pragma unroll
    for (int i = 0; i < 8; ++i)
        sout[pxl][lg*8 + i] = o[i];
    __syncthreads();

    int pix0 = (blockIdx.x * 32) & (HWS - 1);
    int px2 = threadIdx.x & 31;
    int cb = (threadIdx.x >> 5) * 8;
    float* ob = out + (size_t)b * 64 * HWS + pix0 + px2;
#pragma unroll
    for (int i = 0; i < 8; ++i)
        ob[(size_t)(cb + i) * HWS] = sout[px2][cb + i];
}

// ---------------- launcher ----------------
extern "C" void kernel_launch(void* const* d_in, const int* in_sizes, int n_in,
                              void* d_out, int out_size)
{
    const float* nbh = (const float*)d_in[0];
    const float* cen = (const float*)d_in[1];
    const float* mv  = (const float*)d_in[2];
    const float* w1  = (const float*)d_in[3];
    const float* b1  = (const float*)d_in[4];
    const float* w2  = (const float*)d_in[5];
    const float* b2  = (const float*)d_in[6];
    float* out = (float*)d_out;

    __half *nh, *ch, *gH, *cH, *wc, *w2h;
    cudaGetSymbolAddress((void**)&nh,   d_nbh_h);
    cudaGetSymbolAddress((void**)&ch,   d_cen_h);
    cudaGetSymbolAddress((void**)&gH,   d_gH);
    cudaGetSymbolAddress((void**)&cH,   d_cH);
    cudaGetSymbolAddress((void**)&wc,   d_wcomb);
    cudaGetSymbolAddress((void**)&w2h,  d_w2h);

    cudaFuncSetAttribute(conv_tc, cudaFuncAttributeMaxDynamicSharedMemorySize, CONV_SMEM);

    // NCHW -> NHWC fp16 + weight prep
    transpose_prep<<<dim3(HWS/32, CHC/32, 9), dim3(32, 8)>>>(nbh, cen, nh, ch, w1, w2, wc, w2h);

    // HMMA dual conv: CTA M512xN64, pipelined W, smem epilogue
    conv_tc<<<dim3(HH/4, BB, 2), 256, CONV_SMEM>>>(nh, ch, wc, gH, cH);

    // 4 px/warp, 8 warps/block -> 32 px/block; writes NCHW directly
    fused_attn<<<BB*HWS/32, 256>>>(gH, cH, nh, mv, b1, w2h, b2, out);
}

// round 15
// speedup vs baseline: 1.0874x; 1.0302x over previous
#include <cuda_runtime.h>
#include <cuda_fp16.h>
#include <cstdint>

#define BB 4
#define CHC 64
#define HH 128
#define WW 128
#define HWS (HH*WW)

// ---------------- scratch (no allocations allowed) ----------------
__device__ __align__(256) __half d_nbh_h[BB*HWS*CHC];      // NHWC fp16
__device__ __align__(256) __half d_cen_h[BB*HWS*CHC];
__device__ __align__(256) __half d_gH[BB*HWS*CHC];         // conv(nbh) NHWC fp16
__device__ __align__(256) __half d_cH[BB*HWS*CHC];         // conv(cen) NHWC fp16
__device__ __align__(256) __half d_wcomb[2*9*CHC*CHC];     // [conv][tap][o][c] fp16
__device__ __align__(256) __half d_w2h[9*CHC];             // w2 fp16

// ---------------- PTX helpers (portable sm_80+ subset only) ----------------
__device__ __forceinline__ uint32_t smem_u32(const void* p) {
    uint32_t a;
    asm("{ .reg .u64 t; cvta.to.shared.u64 t, %1; cvt.u32.u64 %0, t; }" : "=r"(a) : "l"(p));
    return a;
}
__device__ __forceinline__ void cpa16(uint32_t dst, const void* src) {
    asm volatile("cp.async.cg.shared.global [%0], [%1], 16;" :: "r"(dst), "l"(src));
}
__device__ __forceinline__ void ldsm4(uint32_t* r, uint32_t addr) {
    asm volatile("ldmatrix.sync.aligned.m8n8.x4.shared.b16 {%0,%1,%2,%3}, [%4];"
        : "=r"(r[0]), "=r"(r[1]), "=r"(r[2]), "=r"(r[3]) : "r"(addr));
}
__device__ __forceinline__ void mma_fp16(float* d, const uint32_t* a, const uint32_t* b) {
    asm volatile("mma.sync.aligned.m16n8k16.row.col.f32.f16.f16.f32 "
        "{%0,%1,%2,%3}, {%4,%5,%6,%7}, {%8,%9}, {%0,%1,%2,%3};"
        : "+f"(d[0]), "+f"(d[1]), "+f"(d[2]), "+f"(d[3])
        : "r"(a[0]), "r"(a[1]), "r"(a[2]), "r"(a[3]), "r"(b[0]), "r"(b[1]));
}
__device__ __forceinline__ void h8_to_f(const uint4& u, float* f) {
    const __half2* h = (const __half2*)&u;
    float2 t;
    t = __half22float2(h[0]); f[0] = t.x; f[1] = t.y;
    t = __half22float2(h[1]); f[2] = t.x; f[3] = t.y;
    t = __half22float2(h[2]); f[4] = t.x; f[5] = t.y;
    t = __half22float2(h[3]); f[6] = t.x; f[7] = t.y;
}

// ---------------- transpose NCHW->NHWC (fp16): both tensors per block + weight prep ----------------
// grid: (HWS/32, CHC/32, 5). z 0..3 -> batch (nbh+cen together); z==4 -> weight conversion
__global__ void transpose_prep(const float* __restrict__ nbh, const float* __restrict__ cen,
                               __half* __restrict__ nh, __half* __restrict__ ch,
                               const float* __restrict__ w1, const float* __restrict__ w2,
                               __half* __restrict__ wcomb, __half* __restrict__ w2h)
{
    if (blockIdx.z == 4) {
        int idx = (blockIdx.y * gridDim.x + blockIdx.x) * 256 + threadIdx.y * 32 + threadIdx.x;
        if (idx < 2*9*4096) {
            int c = idx & 63;
            int o = (idx >> 6) & 63;
            int tap = (idx >> 12) % 9;
            int conv = idx / (9 * 4096);
            wcomb[idx] = __float2half(w1[o * 1152 + conv * 576 + c * 9 + tap]);
        } else if (idx < 2*9*4096 + 9*CHC) {
            int k = idx - 2*9*4096;
            w2h[k] = __float2half(w2[k]);
        }
        return;
    }
    __shared__ float tile[2][32][33];
    int b = blockIdx.z;
    int c0 = blockIdx.x * 32;   // pixel tile
    int r0 = blockIdx.y * 32;   // channel tile
    const float* inb0 = nbh + (size_t)b * CHC * HWS;
    const float* inb1 = cen + (size_t)b * CHC * HWS;
#pragma unroll
    for (int i = 0; i < 32; i += 8) {
        size_t off = (size_t)(r0 + threadIdx.y + i) * HWS + (c0 + threadIdx.x);
        tile[0][threadIdx.y + i][threadIdx.x] = inb0[off];
        tile[1][threadIdx.y + i][threadIdx.x] = inb1[off];
    }
    __syncthreads();
#pragma unroll
    for (int i = 0; i < 32; i += 8) {
        int px = c0 + threadIdx.y + i;
        int chn = r0 + threadIdx.x;
        size_t oo = ((size_t)b * HWS + px) * 64 + chn;
        nh[oo] = __float2half(tile[0][threadIdx.x][threadIdx.y + i]);
        ch[oo] = __float2half(tile[1][threadIdx.x][threadIdx.y + i]);
    }
}

// ---------------- HMMA dual conv3x3: CTA M512xN64, pipelined W, smem epilogue (R14 proven) ----------------
#define A_BYTES (780*128)
#define W_OFF   A_BYTES
#define CONV_SMEM (A_BYTES + 9*64*128)

__global__ void __launch_bounds__(256, 1) conv_tc(
    const __half* __restrict__ nbh_h,
    const __half* __restrict__ cen_h,
    const __half* __restrict__ wcomb,
    __half* __restrict__ gH, __half* __restrict__ cH)
{
    extern __shared__ char smem[];
    const int tid = threadIdx.x;
    const int lane = tid & 31;
    const int wid = tid >> 5;
    const int y0 = blockIdx.x * 4;
    const int b = blockIdx.y;
    const int conv = blockIdx.z;
    const __half* src = conv ? cen_h : nbh_h;
    __half* outp = conv ? cH : gH;
    const __half* wsrc = wcomb + (size_t)conv * 9 * 4096;
    const uint32_t sb = smem_u32(smem);

#pragma unroll
    for (int it = 0; it < 24; ++it) {
        int i = tid + it * 256;
        int px = i >> 3, chn = i & 7;
        int ry = px >> 7, x = px & 127;
        int yy = y0 - 1 + ry;
        int pxb = ry * 130 + x + 1;
        uint32_t off = (uint32_t)pxb * 128 + (((uint32_t)chn ^ (pxb & 7)) << 4);
        if ((unsigned)yy < 128u)
            cpa16(sb + off, src + (((size_t)((b * 128 + yy) * 128 + x)) << 6) + chn * 8);
        else
            *(uint4*)(smem + off) = make_uint4(0u, 0u, 0u, 0u);
    }
    if (tid < 96) {
        int pp = tid >> 3;
        int ry = pp >> 1;
        int xpad = (pp & 1) ? 129 : 0;
        int pxb = ry * 130 + xpad;
        int chn = tid & 7;
        uint32_t off = (uint32_t)pxb * 128 + (((uint32_t)chn ^ (pxb & 7)) << 4);
        *(uint4*)(smem + off) = make_uint4(0u, 0u, 0u, 0u);
    }
#pragma unroll
    for (int g = 0; g < 3; ++g) {
#pragma unroll
        for (int it = 0; it < 6; ++it) {
            int i = tid + it * 256 + g * 1536;
            int row = i >> 3, chn = i & 7;
            uint32_t off = W_OFF + (uint32_t)row * 128 + (((uint32_t)chn ^ (row & 7)) << 4);
            cpa16(sb + off, wsrc + row * 64 + chn * 8);
        }
        asm volatile("cp.async.commit_group;");
    }

    float acc[4][8][4];
#pragma unroll
    for (int mt = 0; mt < 4; ++mt)
#pragma unroll
        for (int nt = 0; nt < 8; ++nt)
#pragma unroll
            for (int q = 0; q < 4; ++q) acc[mt][nt][q] = 0.f;

    const int chalfA = lane >> 4;
    const int chalfB = (lane >> 3) & 1;
    const int o_ld = (lane & 7) + ((lane >> 4) << 3);
    const uint32_t bsw = ((uint32_t)(o_ld & 7)) << 4;
    const uint32_t browb = sb + W_OFF + (uint32_t)o_ld * 128;

    int mbase[4], mxx[4];
#pragma unroll
    for (int mt = 0; mt < 4; ++mt) {
        int m = wid * 64 + mt * 16 + (lane & 15);
        mbase[mt] = (m >> 7);
        mxx[mt] = m & 127;
    }

    auto do_taps = [&](int t0) {
#pragma unroll
        for (int tt = 0; tt < 3; ++tt) {
            const int t = t0 + tt;
            const int dy = t / 3 - 1, dx = t % 3 - 1;
            uint32_t arow[4], asw[4];
#pragma unroll
            for (int mt = 0; mt < 4; ++mt) {
                int pxb = (mbase[mt] + dy + 1) * 130 + (mxx[mt] + dx + 1);
                arow[mt] = sb + (uint32_t)pxb * 128;
                asw[mt] = ((uint32_t)(pxb & 7)) << 4;
            }
            const uint32_t browt = browb + (uint32_t)t * 64 * 128;
#pragma unroll
            for (int ks = 0; ks < 4; ++ks) {
                const uint32_t chi = (uint32_t)(ks * 2 + chalfA) << 4;
                uint32_t a[4][4];
#pragma unroll
                for (int mt = 0; mt < 4; ++mt)
                    ldsm4(a[mt], arow[mt] + (chi ^ asw[mt]));
                const uint32_t cbi = (uint32_t)(ks * 2 + chalfB) << 4;
                uint32_t bv[4][4];
#pragma unroll
                for (int j = 0; j < 4; ++j)
                    ldsm4(bv[j], browt + (uint32_t)j * 16 * 128 + (cbi ^ bsw));
#pragma unroll
                for (int mt = 0; mt < 4; ++mt)
#pragma unroll
                    for (int j = 0; j < 4; ++j) {
                        mma_fp16(acc[mt][2*j],   a[mt], &bv[j][0]);
                        mma_fp16(acc[mt][2*j+1], a[mt], &bv[j][2]);
                    }
            }
        }
    };

    asm volatile("cp.async.wait_group 2;");
    __syncthreads();
    do_taps(0);
    asm volatile("cp.async.wait_group 1;");
    __syncthreads();
    do_taps(3);
    asm volatile("cp.async.wait_group 0;");
    __syncthreads();
    do_taps(6);

    // ---- epilogue: acc -> smem (swizzled) -> coalesced STG.128 ----
    __syncthreads();
#pragma unroll
    for (int mt = 0; mt < 4; ++mt)
#pragma unroll
        for (int half = 0; half < 2; ++half) {
            int px = wid * 64 + mt * 16 + (lane >> 2) + half * 8;
#pragma unroll
            for (int nt = 0; nt < 8; ++nt) {
                __half2 hv = __floats2half2_rn(acc[mt][nt][half * 2], acc[mt][nt][half * 2 + 1]);
                uint32_t so = (uint32_t)px * 128 + (((uint32_t)nt ^ (px & 7)) << 4) + (lane & 3) * 4;
                *(uint32_t*)(smem + so) = *(uint32_t*)&hv;
            }
        }
    __syncthreads();
    char* gb = (char*)outp + ((size_t)((b * 128 + y0) * 128) << 7);
#pragma unroll
    for (int it = 0; it < 16; ++it) {
        int i = tid + it * 256;
        int px = i >> 3, chunk = i & 7;
        uint32_t so = (uint32_t)px * 128 + (((uint32_t)(chunk ^ (px & 7))) << 4);
        *(uint4*)(gb + (size_t)px * 128 + chunk * 16) = *(uint4*)(smem + so);
    }
}

// ---------------- fused attn: 4 px/warp (R12 proven); writes NCHW fp32 via smem ----------------
__global__ void __launch_bounds__(256) fused_attn(
    const __half* __restrict__ gH, const __half* __restrict__ cH,
    const __half* __restrict__ nbh_h, const float* __restrict__ mv,
    const float* __restrict__ b1, const __half* __restrict__ w2h,
    const float* __restrict__ b2, float* __restrict__ out)
{
    __shared__ float sout[32][65];

    int wg = blockIdx.x * 8 + (threadIdx.x >> 5);
    int lane = threadIdx.x & 31;
    int grp = lane >> 3;
    int lg = lane & 7;
    int pxl = ((threadIdx.x >> 5) << 2) | grp;
    int pixg = wg * 4 + grp;
    int b = pixg >> 14;
    int pix = pixg & (HWS - 1);
    int y = pix >> 7, x = pix & 127;

    float mvx = mv[(b*2 + 0)*HWS + pix];
    float mvy = mv[(b*2 + 1)*HWS + pix];
    const float inv = 2.0f / 127.0f;
    float gx = fminf(fmaxf(-1.0f + inv*(float)x + mvx*0.5f, -1.0f), 1.0f);
    float gy = fminf(fmaxf(-1.0f + inv*(float)y + mvy*0.5f, -1.0f), 1.0f);
    float px = (gx + 1.0f) * 0.5f * 127.0f;
    float py = (gy + 1.0f) * 0.5f * 127.0f;
    float fx0 = floorf(px), fy0 = floorf(py);
    float wx = px - fx0, wy = py - fy0;
    int ix0 = min(max((int)fx0, 0), WW - 1);
    int iy0 = min(max((int)fy0, 0), HH - 1);
    int ix1 = min(ix0 + 1, WW - 1);
    int iy1 = min(iy0 + 1, HH - 1);

    int pbase = b * HWS;
    const uint4* g4 = (const uint4*)gH;
    uint4 r00 = g4[(size_t)(pbase + iy0*WW + ix0)*8 + lg];
    uint4 r01 = g4[(size_t)(pbase + iy0*WW + ix1)*8 + lg];
    uint4 r10 = g4[(size_t)(pbase + iy1*WW + ix0)*8 + lg];
    uint4 r11 = g4[(size_t)(pbase + iy1*WW + ix1)*8 + lg];
    uint4 rcn = ((const uint4*)cH)[(size_t)(pbase + pix)*8 + lg];
    float w00 = (1.f-wx)*(1.f-wy), w01 = wx*(1.f-wy), w10 = (1.f-wx)*wy, w11 = wx*wy;

    float f00[8], f01[8], f10[8], f11[8], fcn[8];
    h8_to_f(r00, f00); h8_to_f(r01, f01); h8_to_f(r10, f10); h8_to_f(r11, f11);
    h8_to_f(rcn, fcn);
    float4 b1a = ((const float4*)b1)[lg*2];
    float4 b1b = ((const float4*)b1)[lg*2 + 1];
    float b1v[8] = {b1a.x, b1a.y, b1a.z, b1a.w, b1b.x, b1b.y, b1b.z, b1b.w};

    float h1[8];
#pragma unroll
    for (int i = 0; i < 8; ++i) {
        float v = f00[i]*w00 + f01[i]*w01 + f10[i]*w10 + f11[i]*w11 + fcn[i] + b1v[i];
        h1[i] = v >= 0.f ? v : 0.1f*v;
    }

    float part[9];
    const uint4* w24 = (const uint4*)w2h;
#pragma unroll
    for (int j = 0; j < 9; ++j) {
        float wv[8];
        h8_to_f(w24[j*8 + lg], wv);
        part[j] = h1[0]*wv[0] + h1[1]*wv[1] + h1[2]*wv[2] + h1[3]*wv[3]
                + h1[4]*wv[4] + h1[5]*wv[5] + h1[6]*wv[6] + h1[7]*wv[7];
    }
#pragma unroll
    for (int off = 1; off < 8; off <<= 1)
#pragma unroll
        for (int j = 0; j < 9; ++j)
            part[j] += __shfl_xor_sync(0xffffffffu, part[j], off);

    float mx = -1e30f;
#pragma unroll
    for (int j = 0; j < 9; ++j) { part[j] += b2[j]; mx = fmaxf(mx, part[j]); }
    float s = 0.f;
    float attn[9];
#pragma unroll
    for (int j = 0; j < 9; ++j) { attn[j] = __expf(part[j] - mx); s += attn[j]; }
    float sc = 1.0f / (9.0f * s);
#pragma unroll
    for (int j = 0; j < 9; ++j) attn[j] *= sc;

    float wyv[2] = {1.f - wy, wy};
    float wxv[2] = {1.f - wx, wx};
    int d1y = iy1 - iy0;
    int d1x = ix1 - ix0;
    float Wrow[3][4], Wcol[3][4];
#pragma unroll
    for (int dy = 0; dy < 3; ++dy)
#pragma unroll
        for (int r = 0; r < 4; ++r) { Wrow[dy][r] = 0.f; Wcol[dy][r] = 0.f; }
#pragma unroll
    for (int dy = 0; dy < 3; ++dy) {
        int rowlo = iy0 + dy - 1;
        float vlo = (rowlo >= 0 && rowlo < HH) ? wyv[0] : 0.f;
        Wrow[dy][dy] += vlo;
        int rowhi = iy1 + dy - 1;
        float vhi = (rowhi >= 0 && rowhi < HH) ? wyv[1] : 0.f;
        if (d1y) Wrow[dy][dy+1] += vhi; else Wrow[dy][dy] += vhi;

        int collo = ix0 + dy - 1;
        float ulo = (collo >= 0 && collo < WW) ? wxv[0] : 0.f;
        Wcol[dy][dy] += ulo;
        int colhi = ix1 + dy - 1;
        float uhi = (colhi >= 0 && colhi < WW) ? wxv[1] : 0.f;
        if (d1x) Wcol[dy][dy+1] += uhi; else Wcol[dy][dy] += uhi;
    }
    float tmp[3][4];
#pragma unroll
    for (int dy = 0; dy < 3; ++dy)
#pragma unroll
        for (int sx = 0; sx < 4; ++sx) {
            float t = 0.f;
#pragma unroll
            for (int dx = 0; dx < 3; ++dx) t += attn[dy*3 + dx] * Wcol[dx][sx];
            tmp[dy][sx] = t;
        }
    float coeff[16];
#pragma unroll
    for (int r = 0; r < 4; ++r)
#pragma unroll
        for (int sx = 0; sx < 4; ++sx) {
            float t = 0.f;
#pragma unroll
            for (int dy = 0; dy < 3; ++dy) t += Wrow[dy][r] * tmp[dy][sx];
            coeff[r*4 + sx] = t;
        }

    int rowi[4], coli[4];
#pragma unroll
    for (int r = 0; r < 4; ++r) rowi[r] = min(max(iy0 - 1 + r, 0), HH - 1);
#pragma unroll
    for (int sx = 0; sx < 4; ++sx) coli[sx] = min(max(ix0 - 1 + sx, 0), WW - 1);

    const uint4* n4 = (const uint4*)nbh_h;
    float o[8];
#pragma unroll
    for (int i = 0; i < 8; ++i) o[i] = 0.f;
#pragma unroll
    for (int r = 0; r < 4; ++r) {
        size_t rb = (size_t)(pbase + rowi[r]*WW)*8 + lg;
#pragma unroll
        for (int sx = 0; sx < 4; ++sx) {
            uint4 v = n4[rb + (size_t)coli[sx]*8];
            float fv[8];
            h8_to_f(v, fv);
            float cf = coeff[r*4 + sx];
#pragma unroll
            for (int i = 0; i < 8; ++i) o[i] += cf * fv[i];
        }
    }

#pragma unroll
    for (int i = 0; i < 8; ++i)
        sout[pxl][lg*8 + i] = o[i];
    __syncthreads();

    int pix0 = (blockIdx.x * 32) & (HWS - 1);
    int px2 = threadIdx.x & 31;
    int cb = (threadIdx.x >> 5) * 8;
    float* ob = out + (size_t)b * 64 * HWS + pix0 + px2;
#pragma unroll
    for (int i = 0; i < 8; ++i)
        ob[(size_t)(cb + i) * HWS] = sout[px2][cb + i];
}

// ---------------- launcher ----------------
extern "C" void kernel_launch(void* const* d_in, const int* in_sizes, int n_in,
                              void* d_out, int out_size)
{
    const float* nbh = (const float*)d_in[0];
    const float* cen = (const float*)d_in[1];
    const float* mv  = (const float*)d_in[2];
    const float* w1  = (const float*)d_in[3];
    const float* b1  = (const float*)d_in[4];
    const float* w2  = (const float*)d_in[5];
    const float* b2  = (const float*)d_in[6];
    float* out = (float*)d_out;

    __half *nh, *ch, *gH, *cH, *wc, *w2h;
    cudaGetSymbolAddress((void**)&nh,   d_nbh_h);
    cudaGetSymbolAddress((void**)&ch,   d_cen_h);
    cudaGetSymbolAddress((void**)&gH,   d_gH);
    cudaGetSymbolAddress((void**)&cH,   d_cH);
    cudaGetSymbolAddress((void**)&wc,   d_wcomb);
    cudaGetSymbolAddress((void**)&w2h,  d_w2h);

    cudaFuncSetAttribute(conv_tc, cudaFuncAttributeMaxDynamicSharedMemorySize, CONV_SMEM);

    // NCHW -> NHWC fp16 (both tensors per block) + weight prep
    transpose_prep<<<dim3(HWS/32, CHC/32, 5), dim3(32, 8)>>>(nbh, cen, nh, ch, w1, w2, wc, w2h);

    // HMMA dual conv: CTA M512xN64, pipelined W, smem epilogue
    conv_tc<<<dim3(HH/4, BB, 2), 256, CONV_SMEM>>>(nh, ch, wc, gH, cH);

    // 4 px/warp, 8 warps/block -> 32 px/block; writes NCHW directly
    fused_attn<<<BB*HWS/32, 256>>>(gH, cH, nh, mv, b1, w2h, b2, out);
}

// round 16
// speedup vs baseline: 1.0962x; 1.0080x over previous
#include <cuda_runtime.h>
#include <cuda_fp16.h>
#include <cstdint>

#define BB 4
#define CHC 64
#define HH 128
#define WW 128
#define HWS (HH*WW)

// ---------------- scratch (no allocations allowed) ----------------
__device__ __align__(256) __half d_nbh_h[BB*HWS*CHC];      // NHWC fp16
__device__ __align__(256) __half d_cen_h[BB*HWS*CHC];
__device__ __align__(256) __half d_gH[BB*HWS*CHC];         // conv(nbh) NHWC fp16
__device__ __align__(256) __half d_cH[BB*HWS*CHC];         // conv(cen) NHWC fp16
__device__ __align__(256) __half d_wcomb[2*9*CHC*CHC];     // [conv][tap][o][c] fp16
__device__ __align__(256) __half d_w2h[9*CHC];             // w2 fp16

// ---------------- PTX helpers (portable sm_80+ subset only) ----------------
__device__ __forceinline__ uint32_t smem_u32(const void* p) {
    uint32_t a;
    asm("{ .reg .u64 t; cvta.to.shared.u64 t, %1; cvt.u32.u64 %0, t; }" : "=r"(a) : "l"(p));
    return a;
}
__device__ __forceinline__ void cpa16(uint32_t dst, const void* src) {
    asm volatile("cp.async.cg.shared.global [%0], [%1], 16;" :: "r"(dst), "l"(src));
}
__device__ __forceinline__ void ldsm4(uint32_t* r, uint32_t addr) {
    asm volatile("ldmatrix.sync.aligned.m8n8.x4.shared.b16 {%0,%1,%2,%3}, [%4];"
        : "=r"(r[0]), "=r"(r[1]), "=r"(r[2]), "=r"(r[3]) : "r"(addr));
}
__device__ __forceinline__ void mma_fp16(float* d, const uint32_t* a, const uint32_t* b) {
    asm volatile("mma.sync.aligned.m16n8k16.row.col.f32.f16.f16.f32 "
        "{%0,%1,%2,%3}, {%4,%5,%6,%7}, {%8,%9}, {%0,%1,%2,%3};"
        : "+f"(d[0]), "+f"(d[1]), "+f"(d[2]), "+f"(d[3])
        : "r"(a[0]), "r"(a[1]), "r"(a[2]), "r"(a[3]), "r"(b[0]), "r"(b[1]));
}
__device__ __forceinline__ void h8_to_f(const uint4& u, float* f) {
    const __half2* h = (const __half2*)&u;
    float2 t;
    t = __half22float2(h[0]); f[0] = t.x; f[1] = t.y;
    t = __half22float2(h[1]); f[2] = t.x; f[3] = t.y;
    t = __half22float2(h[2]); f[4] = t.x; f[5] = t.y;
    t = __half22float2(h[3]); f[6] = t.x; f[7] = t.y;
}

// ---------------- transpose NCHW->NHWC (fp16): both tensors/block, half2 stores ----------------
// grid: (HWS/32, CHC/32, 5). z 0..3 -> batch (nbh+cen together); z==4 -> weight conversion
__global__ void transpose_prep(const float* __restrict__ nbh, const float* __restrict__ cen,
                               __half* __restrict__ nh, __half* __restrict__ ch,
                               const float* __restrict__ w1, const float* __restrict__ w2,
                               __half* __restrict__ wcomb, __half* __restrict__ w2h)
{
    if (blockIdx.z == 4) {
        int idx = (blockIdx.y * gridDim.x + blockIdx.x) * 256 + threadIdx.y * 32 + threadIdx.x;
        if (idx < 2*9*4096) {
            int c = idx & 63;
            int o = (idx >> 6) & 63;
            int tap = (idx >> 12) % 9;
            int conv = idx / (9 * 4096);
            wcomb[idx] = __float2half(w1[o * 1152 + conv * 576 + c * 9 + tap]);
        } else if (idx < 2*9*4096 + 9*CHC) {
            int k = idx - 2*9*4096;
            w2h[k] = __float2half(w2[k]);
        }
        return;
    }
    __shared__ float tile[2][32][33];
    int b = blockIdx.z;
    int c0 = blockIdx.x * 32;   // pixel tile
    int r0 = blockIdx.y * 32;   // channel tile
    const float* inb0 = nbh + (size_t)b * CHC * HWS;
    const float* inb1 = cen + (size_t)b * CHC * HWS;
#pragma unroll
    for (int i = 0; i < 32; i += 8) {
        size_t off = (size_t)(r0 + threadIdx.y + i) * HWS + (c0 + threadIdx.x);
        tile[0][threadIdx.y + i][threadIdx.x] = inb0[off];
        tile[1][threadIdx.y + i][threadIdx.x] = inb1[off];
    }
    __syncthreads();
    // write: 1024 half2 values (2 tensors x 32 px x 16 channel-pairs), 1 uint32 store each
    int tid = threadIdx.y * 32 + threadIdx.x;
#pragma unroll
    for (int it = 0; it < 4; ++it) {
        int idx = tid + it * 256;
        int pair = idx & 15;
        int pxl = (idx >> 4) & 31;
        int t = idx >> 9;
        float v0 = tile[t][pair * 2][pxl];
        float v1 = tile[t][pair * 2 + 1][pxl];
        __half2 hv = __floats2half2_rn(v0, v1);
        __half* oh = t ? ch : nh;
        *(uint32_t*)(oh + ((size_t)b * HWS + c0 + pxl) * 64 + r0 + pair * 2) = *(uint32_t*)&hv;
    }
}

// ---------------- HMMA dual conv3x3: CTA M512xN64, pipelined W, smem epilogue (R14 proven) ----------------
#define A_BYTES (780*128)
#define W_OFF   A_BYTES
#define CONV_SMEM (A_BYTES + 9*64*128)

__global__ void __launch_bounds__(256, 1) conv_tc(
    const __half* __restrict__ nbh_h,
    const __half* __restrict__ cen_h,
    const __half* __restrict__ wcomb,
    __half* __restrict__ gH, __half* __restrict__ cH)
{
    extern __shared__ char smem[];
    const int tid = threadIdx.x;
    const int lane = tid & 31;
    const int wid = tid >> 5;
    const int y0 = blockIdx.x * 4;
    const int b = blockIdx.y;
    const int conv = blockIdx.z;
    const __half* src = conv ? cen_h : nbh_h;
    __half* outp = conv ? cH : gH;
    const __half* wsrc = wcomb + (size_t)conv * 9 * 4096;
    const uint32_t sb = smem_u32(smem);

#pragma unroll
    for (int it = 0; it < 24; ++it) {
        int i = tid + it * 256;
        int px = i >> 3, chn = i & 7;
        int ry = px >> 7, x = px & 127;
        int yy = y0 - 1 + ry;
        int pxb = ry * 130 + x + 1;
        uint32_t off = (uint32_t)pxb * 128 + (((uint32_t)chn ^ (pxb & 7)) << 4);
        if ((unsigned)yy < 128u)
            cpa16(sb + off, src + (((size_t)((b * 128 + yy) * 128 + x)) << 6) + chn * 8);
        else
            *(uint4*)(smem + off) = make_uint4(0u, 0u, 0u, 0u);
    }
    if (tid < 96) {
        int pp = tid >> 3;
        int ry = pp >> 1;
        int xpad = (pp & 1) ? 129 : 0;
        int pxb = ry * 130 + xpad;
        int chn = tid & 7;
        uint32_t off = (uint32_t)pxb * 128 + (((uint32_t)chn ^ (pxb & 7)) << 4);
        *(uint4*)(smem + off) = make_uint4(0u, 0u, 0u, 0u);
    }
#pragma unroll
    for (int g = 0; g < 3; ++g) {
#pragma unroll
        for (int it = 0; it < 6; ++it) {
            int i = tid + it * 256 + g * 1536;
            int row = i >> 3, chn = i & 7;
            uint32_t off = W_OFF + (uint32_t)row * 128 + (((uint32_t)chn ^ (row & 7)) << 4);
            cpa16(sb + off, wsrc + row * 64 + chn * 8);
        }
        asm volatile("cp.async.commit_group;");
    }

    float acc[4][8][4];
#pragma unroll
    for (int mt = 0; mt < 4; ++mt)
#pragma unroll
        for (int nt = 0; nt < 8; ++nt)
#pragma unroll
            for (int q = 0; q < 4; ++q) acc[mt][nt][q] = 0.f;

    const int chalfA = lane >> 4;
    const int chalfB = (lane >> 3) & 1;
    const int o_ld = (lane & 7) + ((lane >> 4) << 3);
    const uint32_t bsw = ((uint32_t)(o_ld & 7)) << 4;
    const uint32_t browb = sb + W_OFF + (uint32_t)o_ld * 128;

    int mbase[4], mxx[4];
#pragma unroll
    for (int mt = 0; mt < 4; ++mt) {
        int m = wid * 64 + mt * 16 + (lane & 15);
        mbase[mt] = (m >> 7);
        mxx[mt] = m & 127;
    }

    auto do_taps = [&](int t0) {
#pragma unroll
        for (int tt = 0; tt < 3; ++tt) {
            const int t = t0 + tt;
            const int dy = t / 3 - 1, dx = t % 3 - 1;
            uint32_t arow[4], asw[4];
#pragma unroll
            for (int mt = 0; mt < 4; ++mt) {
                int pxb = (mbase[mt] + dy + 1) * 130 + (mxx[mt] + dx + 1);
                arow[mt] = sb + (uint32_t)pxb * 128;
                asw[mt] = ((uint32_t)(pxb & 7)) << 4;
            }
            const uint32_t browt = browb + (uint32_t)t * 64 * 128;
#pragma unroll
            for (int ks = 0; ks < 4; ++ks) {
                const uint32_t chi = (uint32_t)(ks * 2 + chalfA) << 4;
                uint32_t a[4][4];
#pragma unroll
                for (int mt = 0; mt < 4; ++mt)
                    ldsm4(a[mt], arow[mt] + (chi ^ asw[mt]));
                const uint32_t cbi = (uint32_t)(ks * 2 + chalfB) << 4;
                uint32_t bv[4][4];
#pragma unroll
                for (int j = 0; j < 4; ++j)
                    ldsm4(bv[j], browt + (uint32_t)j * 16 * 128 + (cbi ^ bsw));
#pragma unroll
                for (int mt = 0; mt < 4; ++mt)
#pragma unroll
                    for (int j = 0; j < 4; ++j) {
                        mma_fp16(acc[mt][2*j],   a[mt], &bv[j][0]);
                        mma_fp16(acc[mt][2*j+1], a[mt], &bv[j][2]);
                    }
            }
        }
    };

    asm volatile("cp.async.wait_group 2;");
    __syncthreads();
    do_taps(0);
    asm volatile("cp.async.wait_group 1;");
    __syncthreads();
    do_taps(3);
    asm volatile("cp.async.wait_group 0;");
    __syncthreads();
    do_taps(6);

    // ---- epilogue: acc -> smem (swizzled) -> coalesced STG.128 ----
    __syncthreads();
#pragma unroll
    for (int mt = 0; mt < 4; ++mt)
#pragma unroll
        for (int half = 0; half < 2; ++half) {
            int px = wid * 64 + mt * 16 + (lane >> 2) + half * 8;
#pragma unroll
            for (int nt = 0; nt < 8; ++nt) {
                __half2 hv = __floats2half2_rn(acc[mt][nt][half * 2], acc[mt][nt][half * 2 + 1]);
                uint32_t so = (uint32_t)px * 128 + (((uint32_t)nt ^ (px & 7)) << 4) + (lane & 3) * 4;
                *(uint32_t*)(smem + so) = *(uint32_t*)&hv;
            }
        }
    __syncthreads();
    char* gb = (char*)outp + ((size_t)((b * 128 + y0) * 128) << 7);
#pragma unroll
    for (int it = 0; it < 16; ++it) {
        int i = tid + it * 256;
        int px = i >> 3, chunk = i & 7;
        uint32_t so = (uint32_t)px * 128 + (((uint32_t)(chunk ^ (px & 7))) << 4);
        *(uint4*)(gb + (size_t)px * 128 + chunk * 16) = *(uint4*)(smem + so);
    }
}

// ---------------- fused attn: 4 px/warp (R12 proven); writes NCHW fp32 via smem ----------------
__global__ void __launch_bounds__(256) fused_attn(
    const __half* __restrict__ gH, const __half* __restrict__ cH,
    const __half* __restrict__ nbh_h, const float* __restrict__ mv,
    const float* __restrict__ b1, const __half* __restrict__ w2h,
    const float* __restrict__ b2, float* __restrict__ out)
{
    __shared__ float sout[32][65];

    int wg = blockIdx.x * 8 + (threadIdx.x >> 5);
    int lane = threadIdx.x & 31;
    int grp = lane >> 3;
    int lg = lane & 7;
    int pxl = ((threadIdx.x >> 5) << 2) | grp;
    int pixg = wg * 4 + grp;
    int b = pixg >> 14;
    int pix = pixg & (HWS - 1);
    int y = pix >> 7, x = pix & 127;

    float mvx = mv[(b*2 + 0)*HWS + pix];
    float mvy = mv[(b*2 + 1)*HWS + pix];
    const float inv = 2.0f / 127.0f;
    float gx = fminf(fmaxf(-1.0f + inv*(float)x + mvx*0.5f, -1.0f), 1.0f);
    float gy = fminf(fmaxf(-1.0f + inv*(float)y + mvy*0.5f, -1.0f), 1.0f);
    float px = (gx + 1.0f) * 0.5f * 127.0f;
    float py = (gy + 1.0f) * 0.5f * 127.0f;
    float fx0 = floorf(px), fy0 = floorf(py);
    float wx = px - fx0, wy = py - fy0;
    int ix0 = min(max((int)fx0, 0), WW - 1);
    int iy0 = min(max((int)fy0, 0), HH - 1);
    int ix1 = min(ix0 + 1, WW - 1);
    int iy1 = min(iy0 + 1, HH - 1);

    int pbase = b * HWS;
    const uint4* g4 = (const uint4*)gH;
    uint4 r00 = g4[(size_t)(pbase + iy0*WW + ix0)*8 + lg];
    uint4 r01 = g4[(size_t)(pbase + iy0*WW + ix1)*8 + lg];
    uint4 r10 = g4[(size_t)(pbase + iy1*WW + ix0)*8 + lg];
    uint4 r11 = g4[(size_t)(pbase + iy1*WW + ix1)*8 + lg];
    uint4 rcn = ((const uint4*)cH)[(size_t)(pbase + pix)*8 + lg];
    float w00 = (1.f-wx)*(1.f-wy), w01 = wx*(1.f-wy), w10 = (1.f-wx)*wy, w11 = wx*wy;

    float f00[8], f01[8], f10[8], f11[8], fcn[8];
    h8_to_f(r00, f00); h8_to_f(r01, f01); h8_to_f(r10, f10); h8_to_f(r11, f11);
    h8_to_f(rcn, fcn);
    float4 b1a = ((const float4*)b1)[lg*2];
    float4 b1b = ((const float4*)b1)[lg*2 + 1];
    float b1v[8] = {b1a.x, b1a.y, b1a.z, b1a.w, b1b.x, b1b.y, b1b.z, b1b.w};

    float h1[8];
#pragma unroll
    for (int i = 0; i < 8; ++i) {
        float v = f00[i]*w00 + f01[i]*w01 + f10[i]*w10 + f11[i]*w11 + fcn[i] + b1v[i];
        h1[i] = v >= 0.f ? v : 0.1f*v;
    }

    float part[9];
    const uint4* w24 = (const uint4*)w2h;
#pragma unroll
    for (int j = 0; j < 9; ++j) {
        float wv[8];
        h8_to_f(w24[j*8 + lg], wv);
        part[j] = h1[0]*wv[0] + h1[1]*wv[1] + h1[2]*wv[2] + h1[3]*wv[3]
                + h1[4]*wv[4] + h1[5]*wv[5] + h1[6]*wv[6] + h1[7]*wv[7];
    }
#pragma unroll
    for (int off = 1; off < 8; off <<= 1)
#pragma unroll
        for (int j = 0; j < 9; ++j)
            part[j] += __shfl_xor_sync(0xffffffffu, part[j], off);

    float mx = -1e30f;
#pragma unroll
    for (int j = 0; j < 9; ++j) { part[j] += b2[j]; mx = fmaxf(mx, part[j]); }
    float s = 0.f;
    float attn[9];
#pragma unroll
    for (int j = 0; j < 9; ++j) { attn[j] = __expf(part[j] - mx); s += attn[j]; }
    float sc = 1.0f / (9.0f * s);
#pragma unroll
    for (int j = 0; j < 9; ++j) attn[j] *= sc;

    float wyv[2] = {1.f - wy, wy};
    float wxv[2] = {1.f - wx, wx};
    int d1y = iy1 - iy0;
    int d1x = ix1 - ix0;
    float Wrow[3][4], Wcol[3][4];
#pragma unroll
    for (int dy = 0; dy < 3; ++dy)
#pragma unroll
        for (int r = 0; r < 4; ++r) { Wrow[dy][r] = 0.f; Wcol[dy][r] = 0.f; }
#pragma unroll
    for (int dy = 0; dy < 3; ++dy) {
        int rowlo = iy0 + dy - 1;
        float vlo = (rowlo >= 0 && rowlo < HH) ? wyv[0] : 0.f;
        Wrow[dy][dy] += vlo;
        int rowhi = iy1 + dy - 1;
        float vhi = (rowhi >= 0 && rowhi < HH) ? wyv[1] : 0.f;
        if (d1y) Wrow[dy][dy+1] += vhi; else Wrow[dy][dy] += vhi;

        int collo = ix0 + dy - 1;
        float ulo = (collo >= 0 && collo < WW) ? wxv[0] : 0.f;
        Wcol[dy][dy] += ulo;
        int colhi = ix1 + dy - 1;
        float uhi = (colhi >= 0 && colhi < WW) ? wxv[1] : 0.f;
        if (d1x) Wcol[dy][dy+1] += uhi; else Wcol[dy][dy] += uhi;
    }
    float tmp[3][4];
#pragma unroll
    for (int dy = 0; dy < 3; ++dy)
#pragma unroll
        for (int sx = 0; sx < 4; ++sx) {
            float t = 0.f;
#pragma unroll
            for (int dx = 0; dx < 3; ++dx) t += attn[dy*3 + dx] * Wcol[dx][sx];
            tmp[dy][sx] = t;
        }
    float coeff[16];
#pragma unroll
    for (int r = 0; r < 4; ++r)
#pragma unroll
        for (int sx = 0; sx < 4; ++sx) {
            float t = 0.f;
#pragma unroll
            for (int dy = 0; dy < 3; ++dy) t += Wrow[dy][r] * tmp[dy][sx];
            coeff[r*4 + sx] = t;
        }

    int rowi[4], coli[4];
#pragma unroll
    for (int r = 0; r < 4; ++r) rowi[r] = min(max(iy0 - 1 + r, 0), HH - 1);
#pragma unroll
    for (int sx = 0; sx < 4; ++sx) coli[sx] = min(max(ix0 - 1 + sx, 0), WW - 1);

    const uint4* n4 = (const uint4*)nbh_h;
    float o[8];
#pragma unroll
    for (int i = 0; i < 8; ++i) o[i] = 0.f;
#pragma unroll
    for (int r = 0; r < 4; ++r) {
        size_t rb = (size_t)(pbase + rowi[r]*WW)*8 + lg;
#pragma unroll
        for (int sx = 0; sx < 4; ++sx) {
            uint4 v = n4[rb + (size_t)coli[sx]*8];
            float fv[8];
            h8_to_f(v, fv);
            float cf = coeff[r*4 + sx];
#pragma unroll
            for (int i = 0; i < 8; ++i) o[i] += cf * fv[i];
        }
    }

#pragma unroll
    for (int i = 0; i < 8; ++i)
        sout[pxl][lg*8 + i] = o[i];
    __syncthreads();

    int pix0 = (blockIdx.x * 32) & (HWS - 1);
    int px2 = threadIdx.x & 31;
    int cb = (threadIdx.x >> 5) * 8;
    float* ob = out + (size_t)b * 64 * HWS + pix0 + px2;
#pragma unroll
    for (int i = 0; i < 8; ++i)
        ob[(size_t)(cb + i) * HWS] = sout[px2][cb + i];
}

// ---------------- launcher ----------------
extern "C" void kernel_launch(void* const* d_in, const int* in_sizes, int n_in,
                              void* d_out, int out_size)
{
    const float* nbh = (const float*)d_in[0];
    const float* cen = (const float*)d_in[1];
    const float* mv  = (const float*)d_in[2];
    const float* w1  = (const float*)d_in[3];
    const float* b1  = (const float*)d_in[4];
    const float* w2  = (const float*)d_in[5];
    const float* b2  = (const float*)d_in[6];
    float* out = (float*)d_out;

    __half *nh, *ch, *gH, *cH, *wc, *w2h;
    cudaGetSymbolAddress((void**)&nh,   d_nbh_h);
    cudaGetSymbolAddress((void**)&ch,   d_cen_h);
    cudaGetSymbolAddress((void**)&gH,   d_gH);
    cudaGetSymbolAddress((void**)&cH,   d_cH);
    cudaGetSymbolAddress((void**)&wc,   d_wcomb);
    cudaGetSymbolAddress((void**)&w2h,  d_w2h);

    cudaFuncSetAttribute(conv_tc, cudaFuncAttributeMaxDynamicSharedMemorySize, CONV_SMEM);

    // NCHW -> NHWC fp16 (both tensors per block, half2 stores) + weight prep
    transpose_prep<<<dim3(HWS/32, CHC/32, 5), dim3(32, 8)>>>(nbh, cen, nh, ch, w1, w2, wc, w2h);

    // HMMA dual conv: CTA M512xN64, pipelined W, smem epilogue
    conv_tc<<<dim3(HH/4, BB, 2), 256, CONV_SMEM>>>(nh, ch, wc, gH, cH);

    // 4 px/warp, 8 warps/block -> 32 px/block; writes NCHW directly
    fused_attn<<<BB*HWS/32, 256>>>(gH, cH, nh, mv, b1, w2h, b2, out);
}

// round 17
// speedup vs baseline: 1.0967x; 1.0005x over previous
#include <cuda_runtime.h>
#include <cuda_fp16.h>
#include <cstdint>

#define BB 4
#define CHC 64
#define HH 128
#define WW 128
#define HWS (HH*WW)

// ---------------- scratch (no allocations allowed) ----------------
__device__ __align__(256) __half d_nbh_h[BB*HWS*CHC];      // NHWC fp16
__device__ __align__(256) __half d_cen_h[BB*HWS*CHC];
__device__ __align__(256) __half d_gH[BB*HWS*CHC];         // conv(nbh) NHWC fp16
__device__ __align__(256) __half d_cH[BB*HWS*CHC];         // conv(cen) NHWC fp16
__device__ __align__(256) __half d_wcomb[2*9*CHC*CHC];     // [conv][tap][o][c] fp16
__device__ __align__(256) __half d_w2h[9*CHC];             // w2 fp16

// ---------------- PTX helpers (portable sm_80+ subset only) ----------------
__device__ __forceinline__ uint32_t smem_u32(const void* p) {
    uint32_t a;
    asm("{ .reg .u64 t; cvta.to.shared.u64 t, %1; cvt.u32.u64 %0, t; }" : "=r"(a) : "l"(p));
    return a;
}
__device__ __forceinline__ void cpa16(uint32_t dst, const void* src) {
    asm volatile("cp.async.cg.shared.global [%0], [%1], 16;" :: "r"(dst), "l"(src));
}
__device__ __forceinline__ void ldsm4(uint32_t* r, uint32_t addr) {
    asm volatile("ldmatrix.sync.aligned.m8n8.x4.shared.b16 {%0,%1,%2,%3}, [%4];"
        : "=r"(r[0]), "=r"(r[1]), "=r"(r[2]), "=r"(r[3]) : "r"(addr));
}
__device__ __forceinline__ void mma_fp16(float* d, const uint32_t* a, const uint32_t* b) {
    asm volatile("mma.sync.aligned.m16n8k16.row.col.f32.f16.f16.f32 "
        "{%0,%1,%2,%3}, {%4,%5,%6,%7}, {%8,%9}, {%0,%1,%2,%3};"
        : "+f"(d[0]), "+f"(d[1]), "+f"(d[2]), "+f"(d[3])
        : "r"(a[0]), "r"(a[1]), "r"(a[2]), "r"(a[3]), "r"(b[0]), "r"(b[1]));
}
__device__ __forceinline__ void h8_to_f(const uint4& u, float* f) {
    const __half2* h = (const __half2*)&u;
    float2 t;
    t = __half22float2(h[0]); f[0] = t.x; f[1] = t.y;
    t = __half22float2(h[1]); f[2] = t.x; f[3] = t.y;
    t = __half22float2(h[2]); f[4] = t.x; f[5] = t.y;
    t = __half22float2(h[3]); f[6] = t.x; f[7] = t.y;
}

// ---------------- transpose NCHW->NHWC (fp16), one tensor, all 64 channels/block ----------------
// grid: (HWS/32, 1, Z). z 0..3 -> batch; z==4 (nbh launch only) -> weight prep.
__global__ void transpose_one(const float* __restrict__ in, __half* __restrict__ outh,
                              const float* __restrict__ w1, const float* __restrict__ w2,
                              __half* __restrict__ wcomb, __half* __restrict__ w2h)
{
    if (blockIdx.z == 4) {
        int idx = blockIdx.x * 256 + threadIdx.y * 32 + threadIdx.x;
        if (idx < 2*9*4096) {
            int c = idx & 63;
            int o = (idx >> 6) & 63;
            int tap = (idx >> 12) % 9;
            int conv = idx / (9 * 4096);
            wcomb[idx] = __float2half(w1[o * 1152 + conv * 576 + c * 9 + tap]);
        } else if (idx < 2*9*4096 + 9*CHC) {
            int k = idx - 2*9*4096;
            w2h[k] = __float2half(w2[k]);
        }
        return;
    }
    __shared__ float tile[2][33][33];   // [ch-half][ch-row][px], padded both dims
    int b = blockIdx.z;
    int c0 = blockIdx.x * 32;           // pixel offset
    const float* inb = in + (size_t)b * CHC * HWS;
#pragma unroll
    for (int i = 0; i < 32; i += 8) {
        size_t off = (size_t)(threadIdx.y + i) * HWS + c0 + threadIdx.x;
        tile[0][threadIdx.y + i][threadIdx.x] = inb[off];
        tile[1][threadIdx.y + i][threadIdx.x] = inb[off + (size_t)32 * HWS];
    }
    __syncthreads();
    int tid = threadIdx.y * 32 + threadIdx.x;
#pragma unroll
    for (int it = 0; it < 4; ++it) {
        int idx = tid + it * 256;       // 1024 half2 (32 px x 32 ch-pairs)
        int pair = idx & 31;
        int pxl = idx >> 5;
        int hf = pair >> 4;
        int pr = pair & 15;
        float v0 = tile[hf][pr * 2][pxl];
        float v1 = tile[hf][pr * 2 + 1][pxl];
        __half2 hv = __floats2half2_rn(v0, v1);
        *(uint32_t*)(outh + ((size_t)b * HWS + c0 + pxl) * 64 + hf * 32 + pr * 2) = *(uint32_t*)&hv;
    }
}

// ---------------- HMMA dual conv3x3: CTA M512xN64, pipelined W, smem epilogue ----------------
#define A_BYTES (780*128)
#define W_OFF   A_BYTES
#define CONV_SMEM (A_BYTES + 9*64*128)

__global__ void __launch_bounds__(256, 1) conv_tc(
    const __half* __restrict__ nbh_h,
    const __half* __restrict__ cen_h,
    const __half* __restrict__ wcomb,
    __half* __restrict__ gH, __half* __restrict__ cH,
    int conv)
{
    extern __shared__ char smem[];
    const int tid = threadIdx.x;
    const int lane = tid & 31;
    const int wid = tid >> 5;
    const int y0 = blockIdx.x * 4;
    const int b = blockIdx.y;
    const __half* src = conv ? cen_h : nbh_h;
    __half* outp = conv ? cH : gH;
    const __half* wsrc = wcomb + (size_t)conv * 9 * 4096;
    const uint32_t sb = smem_u32(smem);

#pragma unroll
    for (int it = 0; it < 24; ++it) {
        int i = tid + it * 256;
        int px = i >> 3, chn = i & 7;
        int ry = px >> 7, x = px & 127;
        int yy = y0 - 1 + ry;
        int pxb = ry * 130 + x + 1;
        uint32_t off = (uint32_t)pxb * 128 + (((uint32_t)chn ^ (pxb & 7)) << 4);
        if ((unsigned)yy < 128u)
            cpa16(sb + off, src + (((size_t)((b * 128 + yy) * 128 + x)) << 6) + chn * 8);
        else
            *(uint4*)(smem + off) = make_uint4(0u, 0u, 0u, 0u);
    }
    if (tid < 96) {
        int pp = tid >> 3;
        int ry = pp >> 1;
        int xpad = (pp & 1) ? 129 : 0;
        int pxb = ry * 130 + xpad;
        int chn = tid & 7;
        uint32_t off = (uint32_t)pxb * 128 + (((uint32_t)chn ^ (pxb & 7)) << 4);
        *(uint4*)(smem + off) = make_uint4(0u, 0u, 0u, 0u);
    }
#pragma unroll
    for (int g = 0; g < 3; ++g) {
#pragma unroll
        for (int it = 0; it < 6; ++it) {
            int i = tid + it * 256 + g * 1536;
            int row = i >> 3, chn = i & 7;
            uint32_t off = W_OFF + (uint32_t)row * 128 + (((uint32_t)chn ^ (row & 7)) << 4);
            cpa16(sb + off, wsrc + row * 64 + chn * 8);
        }
        asm volatile("cp.async.commit_group;");
    }

    float acc[4][8][4];
#pragma unroll
    for (int mt = 0; mt < 4; ++mt)
#pragma unroll
        for (int nt = 0; nt < 8; ++nt)
#pragma unroll
            for (int q = 0; q < 4; ++q) acc[mt][nt][q] = 0.f;

    const int chalfA = lane >> 4;
    const int chalfB = (lane >> 3) & 1;
    const int o_ld = (lane & 7) + ((lane >> 4) << 3);
    const uint32_t bsw = ((uint32_t)(o_ld & 7)) << 4;
    const uint32_t browb = sb + W_OFF + (uint32_t)o_ld * 128;

    int mbase[4], mxx[4];
#pragma unroll
    for (int mt = 0; mt < 4; ++mt) {
        int m = wid * 64 + mt * 16 + (lane & 15);
        mbase[mt] = (m >> 7);
        mxx[mt] = m & 127;
    }

    auto do_taps = [&](int t0) {
#pragma unroll
        for (int tt = 0; tt < 3; ++tt) {
            const int t = t0 + tt;
            const int dy = t / 3 - 1, dx = t % 3 - 1;
            uint32_t arow[4], asw[4];
#pragma unroll
            for (int mt = 0; mt < 4; ++mt) {
                int pxb = (mbase[mt] + dy + 1) * 130 + (mxx[mt] + dx + 1);
                arow[mt] = sb + (uint32_t)pxb * 128;
                asw[mt] = ((uint32_t)(pxb & 7)) << 4;
            }
            const uint32_t browt = browb + (uint32_t)t * 64 * 128;
#pragma unroll
            for (int ks = 0; ks < 4; ++ks) {
                const uint32_t chi = (uint32_t)(ks * 2 + chalfA) << 4;
                uint32_t a[4][4];
#pragma unroll
                for (int mt = 0; mt < 4; ++mt)
                    ldsm4(a[mt], arow[mt] + (chi ^ asw[mt]));
                const uint32_t cbi = (uint32_t)(ks * 2 + chalfB) << 4;
                uint32_t bv[4][4];
#pragma unroll
                for (int j = 0; j < 4; ++j)
                    ldsm4(bv[j], browt + (uint32_t)j * 16 * 128 + (cbi ^ bsw));
#pragma unroll
                for (int mt = 0; mt < 4; ++mt)
#pragma unroll
                    for (int j = 0; j < 4; ++j) {
                        mma_fp16(acc[mt][2*j],   a[mt], &bv[j][0]);
                        mma_fp16(acc[mt][2*j+1], a[mt], &bv[j][2]);
                    }
            }
        }
    };

    asm volatile("cp.async.wait_group 2;");
    __syncthreads();
    do_taps(0);
    asm volatile("cp.async.wait_group 1;");
    __syncthreads();
    do_taps(3);
    asm volatile("cp.async.wait_group 0;");
    __syncthreads();
    do_taps(6);

    // ---- epilogue: acc -> smem (swizzled) -> coalesced STG.128 ----
    __syncthreads();
#pragma unroll
    for (int mt = 0; mt < 4; ++mt)
#pragma unroll
        for (int half = 0; half < 2; ++half) {
            int px = wid * 64 + mt * 16 + (lane >> 2) + half * 8;
#pragma unroll
            for (int nt = 0; nt < 8; ++nt) {
                __half2 hv = __floats2half2_rn(acc[mt][nt][half * 2], acc[mt][nt][half * 2 + 1]);
                uint32_t so = (uint32_t)px * 128 + (((uint32_t)nt ^ (px & 7)) << 4) + (lane & 3) * 4;
                *(uint32_t*)(smem + so) = *(uint32_t*)&hv;
            }
        }
    __syncthreads();
    char* gb = (char*)outp + ((size_t)((b * 128 + y0) * 128) << 7);
#pragma unroll
    for (int it = 0; it < 16; ++it) {
        int i = tid + it * 256;
        int px = i >> 3, chunk = i & 7;
        uint32_t so = (uint32_t)px * 128 + (((uint32_t)(chunk ^ (px & 7))) << 4);
        *(uint4*)(gb + (size_t)px * 128 + chunk * 16) = *(uint4*)(smem + so);
    }
}

// ---------------- fused attn: 4 px/warp (R12 proven); writes NCHW fp32 via smem ----------------
__global__ void __launch_bounds__(256) fused_attn(
    const __half* __restrict__ gH, const __half* __restrict__ cH,
    const __half* __restrict__ nbh_h, const float* __restrict__ mv,
    const float* __restrict__ b1, const __half* __restrict__ w2h,
    const float* __restrict__ b2, float* __restrict__ out)
{
    __shared__ float sout[32][65];

    int wg = blockIdx.x * 8 + (threadIdx.x >> 5);
    int lane = threadIdx.x & 31;
    int grp = lane >> 3;
    int lg = lane & 7;
    int pxl = ((threadIdx.x >> 5) << 2) | grp;
    int pixg = wg * 4 + grp;
    int b = pixg >> 14;
    int pix = pixg & (HWS - 1);
    int y = pix >> 7, x = pix & 127;

    float mvx = mv[(b*2 + 0)*HWS + pix];
    float mvy = mv[(b*2 + 1)*HWS + pix];
    const float inv = 2.0f / 127.0f;
    float gx = fminf(fmaxf(-1.0f + inv*(float)x + mvx*0.5f, -1.0f), 1.0f);
    float gy = fminf(fmaxf(-1.0f + inv*(float)y + mvy*0.5f, -1.0f), 1.0f);
    float px = (gx + 1.0f) * 0.5f * 127.0f;
    float py = (gy + 1.0f) * 0.5f * 127.0f;
    float fx0 = floorf(px), fy0 = floorf(py);
    float wx = px - fx0, wy = py - fy0;
    int ix0 = min(max((int)fx0, 0), WW - 1);
    int iy0 = min(max((int)fy0, 0), HH - 1);
    int ix1 = min(ix0 + 1, WW - 1);
    int iy1 = min(iy0 + 1, HH - 1);

    int pbase = b * HWS;
    const uint4* g4 = (const uint4*)gH;
    uint4 r00 = g4[(size_t)(pbase + iy0*WW + ix0)*8 + lg];
    uint4 r01 = g4[(size_t)(pbase + iy0*WW + ix1)*8 + lg];
    uint4 r10 = g4[(size_t)(pbase + iy1*WW + ix0)*8 + lg];
    uint4 r11 = g4[(size_t)(pbase + iy1*WW + ix1)*8 + lg];
    uint4 rcn = ((const uint4*)cH)[(size_t)(pbase + pix)*8 + lg];
    float w00 = (1.f-wx)*(1.f-wy), w01 = wx*(1.f-wy), w10 = (1.f-wx)*wy, w11 = wx*wy;

    float f00[8], f01[8], f10[8], f11[8], fcn[8];
    h8_to_f(r00, f00); h8_to_f(r01, f01); h8_to_f(r10, f10); h8_to_f(r11, f11);
    h8_to_f(rcn, fcn);
    float4 b1a = ((const float4*)b1)[lg*2];
    float4 b1b = ((const float4*)b1)[lg*2 + 1];
    float b1v[8] = {b1a.x, b1a.y, b1a.z, b1a.w, b1b.x, b1b.y, b1b.z, b1b.w};

    float h1[8];
#pragma unroll
    for (int i = 0; i < 8; ++i) {
        float v = f00[i]*w00 + f01[i]*w01 + f10[i]*w10 + f11[i]*w11 + fcn[i] + b1v[i];
        h1[i] = v >= 0.f ? v : 0.1f*v;
    }

    float part[9];
    const uint4* w24 = (const uint4*)w2h;
#pragma unroll
    for (int j = 0; j < 9; ++j) {
        float wv[8];
        h8_to_f(w24[j*8 + lg], wv);
        part[j] = h1[0]*wv[0] + h1[1]*wv[1] + h1[2]*wv[2] + h1[3]*wv[3]
                + h1[4]*wv[4] + h1[5]*wv[5] + h1[6]*wv[6] + h1[7]*wv[7];
    }
#pragma unroll
    for (int off = 1; off < 8; off <<= 1)
#pragma unroll
        for (int j = 0; j < 9; ++j)
            part[j] += __shfl_xor_sync(0xffffffffu, part[j], off);

    float mx = -1e30f;
#pragma unroll
    for (int j = 0; j < 9; ++j) { part[j] += b2[j]; mx = fmaxf(mx, part[j]); }
    float s = 0.f;
    float attn[9];
#pragma unroll
    for (int j = 0; j < 9; ++j) { attn[j] = __expf(part[j] - mx); s += attn[j]; }
    float sc = 1.0f / (9.0f * s);
#pragma unroll
    for (int j = 0; j < 9; ++j) attn[j] *= sc;

    float wyv[2] = {1.f - wy, wy};
    float wxv[2] = {1.f - wx, wx};
    int d1y = iy1 - iy0;
    int d1x = ix1 - ix0;
    float Wrow[3][4], Wcol[3][4];
#pragma unroll
    for (int dy = 0; dy < 3; ++dy)
#pragma unroll
        for (int r = 0; r < 4; ++r) { Wrow[dy][r] = 0.f; Wcol[dy][r] = 0.f; }
#pragma unroll
    for (int dy = 0; dy < 3; ++dy) {
        int rowlo = iy0 + dy - 1;
        float vlo = (rowlo >= 0 && rowlo < HH) ? wyv[0] : 0.f;
        Wrow[dy][dy] += vlo;
        int rowhi = iy1 + dy - 1;
        float vhi = (rowhi >= 0 && rowhi < HH) ? wyv[1] : 0.f;
        if (d1y) Wrow[dy][dy+1] += vhi; else Wrow[dy][dy] += vhi;

        int collo = ix0 + dy - 1;
        float ulo = (collo >= 0 && collo < WW) ? wxv[0] : 0.f;
        Wcol[dy][dy] += ulo;
        int colhi = ix1 + dy - 1;
        float uhi = (colhi >= 0 && colhi < WW) ? wxv[1] : 0.f;
        if (d1x) Wcol[dy][dy+1] += uhi; else Wcol[dy][dy] += uhi;
    }
    float tmp[3][4];
#pragma unroll
    for (int dy = 0; dy < 3; ++dy)
#pragma unroll
        for (int sx = 0; sx < 4; ++sx) {
            float t = 0.f;
#pragma unroll
            for (int dx = 0; dx < 3; ++dx) t += attn[dy*3 + dx] * Wcol[dx][sx];
            tmp[dy][sx] = t;
        }
    float coeff[16];
#pragma unroll
    for (int r = 0; r < 4; ++r)
#pragma unroll
        for (int sx = 0; sx < 4; ++sx) {
            float t = 0.f;
#pragma unroll
            for (int dy = 0; dy < 3; ++dy) t += Wrow[dy][r] * tmp[dy][sx];
            coeff[r*4 + sx] = t;
        }

    int rowi[4], coli[4];
#pragma unroll
    for (int r = 0; r < 4; ++r) rowi[r] = min(max(iy0 - 1 + r, 0), HH - 1);
#pragma unroll
    for (int sx = 0; sx < 4; ++sx) coli[sx] = min(max(ix0 - 1 + sx, 0), WW - 1);

    const uint4* n4 = (const uint4*)nbh_h;
    float o[8];
#pragma unroll
    for (int i = 0; i < 8; ++i) o[i] = 0.f;
#pragma unroll
    for (int r = 0; r < 4; ++r) {
        size_t rb = (size_t)(pbase + rowi[r]*WW)*8 + lg;
#pragma unroll
        for (int sx = 0; sx < 4; ++sx) {
            uint4 v = n4[rb + (size_t)coli[sx]*8];
            float fv[8];
            h8_to_f(v, fv);
            float cf = coeff[r*4 + sx];
#pragma unroll
            for (int i = 0; i < 8; ++i) o[i] += cf * fv[i];
        }
    }

#pragma unroll
    for (int i = 0; i < 8; ++i)
        sout[pxl][lg*8 + i] = o[i];
    __syncthreads();

    int pix0 = (blockIdx.x * 32) & (HWS - 1);
    int px2 = threadIdx.x & 31;
    int cb = (threadIdx.x >> 5) * 8;
    float* ob = out + (size_t)b * 64 * HWS + pix0 + px2;
#pragma unroll
    for (int i = 0; i < 8; ++i)
        ob[(size_t)(cb + i) * HWS] = sout[px2][cb + i];
}

// ---------------- launcher: forked-stream graph ----------------
extern "C" void kernel_launch(void* const* d_in, const int* in_sizes, int n_in,
                              void* d_out, int out_size)
{
    const float* nbh = (const float*)d_in[0];
    const float* cen = (const float*)d_in[1];
    const float* mv  = (const float*)d_in[2];
    const float* w1  = (const float*)d_in[3];
    const float* b1  = (const float*)d_in[4];
    const float* w2  = (const float*)d_in[5];
    const float* b2  = (const float*)d_in[6];
    float* out = (float*)d_out;

    __half *nh, *ch, *gH, *cH, *wc, *w2h;
    cudaGetSymbolAddress((void**)&nh,   d_nbh_h);
    cudaGetSymbolAddress((void**)&ch,   d_cen_h);
    cudaGetSymbolAddress((void**)&gH,   d_gH);
    cudaGetSymbolAddress((void**)&cH,   d_cH);
    cudaGetSymbolAddress((void**)&wc,   d_wcomb);
    cudaGetSymbolAddress((void**)&w2h,  d_w2h);

    static cudaStream_t s1 = nullptr;
    static cudaEvent_t ev0 = nullptr, ev1 = nullptr;
    if (!s1) {
        cudaStreamCreateWithFlags(&s1, cudaStreamNonBlocking);
        cudaEventCreateWithFlags(&ev0, cudaEventDisableTiming);
        cudaEventCreateWithFlags(&ev1, cudaEventDisableTiming);
        cudaFuncSetAttribute(conv_tc, cudaFuncAttributeMaxDynamicSharedMemorySize, CONV_SMEM);
    }

    // T_nbh + weight prep (main stream)
    transpose_one<<<dim3(HWS/32, 1, 5), dim3(32, 8)>>>(nbh, nh, w1, w2, wc, w2h);
    cudaEventRecord(ev0, 0);

    // T_cen forked onto s1 (overlaps conv_nbh)
    cudaStreamWaitEvent(s1, ev0, 0);
    transpose_one<<<dim3(HWS/32, 1, 4), dim3(32, 8), 0, s1>>>(cen, ch, w1, w2, wc, w2h);
    cudaEventRecord(ev1, s1);

    // conv_nbh on main stream (depends on T_nbh+prep only)
    conv_tc<<<dim3(HH/4, BB, 1), 256, CONV_SMEM>>>(nh, ch, wc, gH, cH, 0);

    // join: conv_cen needs T_cen
    cudaStreamWaitEvent(0, ev1, 0);
    conv_tc<<<dim3(HH/4, BB, 1), 256, CONV_SMEM>>>(nh, ch, wc, gH, cH, 1);

    // fused attention
    fused_attn<<<BB*HWS/32, 256>>>(gH, cH, nh, mv, b1, w2h, b2, out);
}